// round 12
// baseline (speedup 1.0000x reference)
#include <cuda_runtime.h>
#include <cuda_bf16.h>
#include <cstdint>

#define NB 16
#define NT 9
#define NYX 256
#define SP 65536
#define C1 10
#define C2 20
#define C3 54

#define OFF_XOUT 0
#define OFF_KAP  16
#define OFF_M    9437200
#define OFF_H    28311568

#define TSK 288   // skewed tile row stride

__device__ float g_p1[NB * C1 * SP];
__device__ float g_p2[NB * C2 * SP];
__device__ float g_p3[NB * C3 * SP];
__device__ float g_xg[NB * NT * SP];
__device__ float g_w [NB * NT * SP];
__device__ float g_v [NB * NT * SP];
__device__ float g_kg [NB * NT * SP];
__device__ float g_m1 [NB * NT * SP];
__device__ float g_m2 [NB * NT * SP];
__device__ float g_part[NB * 160];
// bf16 A-fragments: conv1 slots 0..5 (MT1,KS6); conv2 6..17 (MT2,KS6);
// conv3 18..65 (4 m-tiles x KS12).
__device__ uint4 g_wfrag[66 * 32 * 2];

__device__ __forceinline__ float sp10(float x) {
    float z = 10.0f * x;
    return (fmaxf(z, 0.0f) + log1pf(expf(-fabsf(z)))) * 0.1f;
}
__device__ __forceinline__ uint32_t bfpack(float lo, float hi) {
    uint32_t r; asm("cvt.rn.bf16x2.f32 %0, %1, %2;" : "=r"(r) : "f"(hi), "f"(lo));
    return r;
}
__device__ __forceinline__ float bf_lo(uint32_t h) { return __uint_as_float(h << 16); }
__device__ __forceinline__ float bf_hi(uint32_t h) { return __uint_as_float(h & 0xFFFF0000u); }

__device__ __forceinline__ void mma_bf16(float* d, const uint32_t* a, const uint32_t* b) {
    asm("mma.sync.aligned.m16n8k16.row.col.f32.bf16.bf16.f32 "
        "{%0,%1,%2,%3}, {%4,%5,%6,%7}, {%8,%9}, {%0,%1,%2,%3};"
        : "+f"(d[0]), "+f"(d[1]), "+f"(d[2]), "+f"(d[3])
        : "r"(a[0]), "r"(a[1]), "r"(a[2]), "r"(a[3]), "r"(b[0]), "r"(b[1]));
}

// ---------------------------------------------------------------------------
__global__ void prep_w_k(const float* __restrict__ w1,
                         const float* __restrict__ w2,
                         const float* __restrict__ w3) {
    int idx = blockIdx.x * blockDim.x + threadIdx.x;
    if (idx >= 66 * 32) return;
    int lane = idx & 31;
    int slot = idx >> 5;
    const float* w; int K, COUT, mt, ks;
    if (slot < 6)       { w = w1; K = 81;  COUT = C1; mt = 0;               ks = slot; }
    else if (slot < 18) { w = w2; K = 90;  COUT = C2; int s = slot - 6;  mt = s / 6;  ks = s % 6; }
    else                { w = w3; K = 180; COUT = C3; int s = slot - 18; mt = s / 12; ks = s % 12; }
    int g = lane >> 2, tig = lane & 3;
    uint32_t hi[4], lo[4];
#pragma unroll
    for (int i = 0; i < 4; i++) {
        int row = mt * 16 + g + (i & 1) * 8;
        int k   = ks * 16 + (i >> 1) * 8 + 2 * tig;
        float w0 = (row < COUT && k     < K) ? w[row * K + k]     : 0.0f;
        float w1v = (row < COUT && k + 1 < K) ? w[row * K + k + 1] : 0.0f;
        uint32_t h = bfpack(w0, w1v);
        hi[i] = h;
        lo[i] = bfpack(w0 - bf_lo(h), w1v - bf_hi(h));
    }
    int base = (slot * 32 + lane) * 2;
    g_wfrag[base]     = make_uint4(hi[0], hi[1], hi[2], hi[3]);
    g_wfrag[base + 1] = make_uint4(lo[0], lo[1], lo[2], lo[3]);
}

// ---------------------------------------------------------------------------
// Generic conv3x3, bf16 m16n8k16 3-pass. blockIdx.x = cout chunk of MT m-tiles.
// ---------------------------------------------------------------------------
template <int CIN, bool RELU_IN, int MT, int KS, int COUT, int WOFF, int MAXB>
__global__ void __launch_bounds__(256, MAXB)
conv_mma_k(const float* __restrict__ in, float* __restrict__ out) {
    extern __shared__ float sh[];
    const int ZR = CIN * 3;
    float* tile = sh;
    int*   koff = (int*)(sh + (ZR + 1) * TSK);

    const int b  = blockIdx.z;
    const int y0 = blockIdx.y;
    const int chunk = blockIdx.x;
    const int tid = threadIdx.y * 32 + threadIdx.x;

    const float* inb = in + (size_t)b * CIN * SP;
    for (int idx = tid; idx < CIN * 3 * 258; idx += 256) {
        int c  = idx % 258;
        int rr = (idx / 258) % 3;
        int ci = idx / 774;
        int gy = y0 - 1 + rr;
        int gx = c - 1;
        float v = 0.0f;
        if (gy >= 0 && gy < NYX && gx >= 0 && gx < NYX) {
            v = inb[ci * SP + gy * NYX + gx];
            if (RELU_IN) v = fmaxf(v, 0.0f);
        }
        tile[(ci * 3 + rr) * TSK + 8 * rr + c] = v;
    }
    for (int i = tid; i < TSK; i += 256) tile[ZR * TSK + i] = 0.0f;
    for (int k = tid; k < KS * 16; k += 256) {
        if (k < CIN * 9) {
            int ci = k / 9, r = k % 9;
            int ky = r / 3;
            koff[k] = (ci * 3 + ky) * TSK + 8 * ky + (r % 3);
        } else {
            koff[k] = ZR * TSK;
        }
    }
    __syncthreads();

    const int warp = threadIdx.y;
    const int lane = threadIdx.x;
    const int g = lane >> 2, tig = lane & 3;
    const int nbase = warp * 32;

    float acc[MT][4][4];
#pragma unroll
    for (int m = 0; m < MT; m++)
#pragma unroll
        for (int n = 0; n < 4; n++)
#pragma unroll
            for (int q = 0; q < 4; q++) acc[m][n][q] = 0.0f;

    for (int ks = 0; ks < KS; ks++) {
        int o00 = koff[ks * 16 + 2 * tig];
        int o01 = koff[ks * 16 + 2 * tig + 1];
        int o10 = koff[ks * 16 + 8 + 2 * tig];
        int o11 = koff[ks * 16 + 8 + 2 * tig + 1];
        uint32_t bhi[4][2], blo[4][2];
#pragma unroll
        for (int nt = 0; nt < 4; nt++) {
            int n = nbase + nt * 8 + g;
            float x00 = tile[o00 + n], x01 = tile[o01 + n];
            float x10 = tile[o10 + n], x11 = tile[o11 + n];
            uint32_t h0 = bfpack(x00, x01);
            uint32_t h1 = bfpack(x10, x11);
            bhi[nt][0] = h0;
            bhi[nt][1] = h1;
            blo[nt][0] = bfpack(x00 - bf_lo(h0), x01 - bf_hi(h0));
            blo[nt][1] = bfpack(x10 - bf_lo(h1), x11 - bf_hi(h1));
        }
#pragma unroll
        for (int mt = 0; mt < MT; mt++) {
            int base = ((WOFF + (chunk * MT + mt) * KS + ks) * 32 + lane) * 2;
            uint4 ah = g_wfrag[base];
            uint4 al = g_wfrag[base + 1];
            uint32_t ahi[4] = { ah.x, ah.y, ah.z, ah.w };
            uint32_t alo[4] = { al.x, al.y, al.z, al.w };
#pragma unroll
            for (int nt = 0; nt < 4; nt++) {
                mma_bf16(acc[mt][nt], ahi, bhi[nt]);
                mma_bf16(acc[mt][nt], ahi, blo[nt]);
                mma_bf16(acc[mt][nt], alo, bhi[nt]);
            }
        }
    }

#pragma unroll
    for (int mt = 0; mt < MT; mt++) {
        int co0 = (chunk * MT + mt) * 16 + g;
#pragma unroll
        for (int nt = 0; nt < 4; nt++) {
            int px = nbase + nt * 8 + 2 * tig;
            float* op = out + ((size_t)b * COUT + co0) * SP + (size_t)y0 * NYX + px;
            if (co0 < COUT)
                *reinterpret_cast<float2*>(op) = make_float2(acc[mt][nt][0], acc[mt][nt][1]);
            if (co0 + 8 < COUT)
                *reinterpret_cast<float2*>(op + (size_t)8 * SP) = make_float2(acc[mt][nt][2], acc[mt][nt][3]);
        }
    }
}

// ---------------------------------------------------------------------------
__global__ void epiA_scramble_k(float* __restrict__ out) {
    __shared__ float shk[2304], shm1[2304], shm2[2304];
    int b = blockIdx.y;
    int chunk = blockIdx.x;
    int L0 = chunk * 2304;
    int s0 = chunk * 256;
    const float* src = g_p3 + (size_t)b * C3 * SP;
    float* okap = out + OFF_KAP + (size_t)b * 9 * SP;
    float* om   = out + OFF_M   + (size_t)b * 18 * SP;
#pragma unroll
    for (int it = 0; it < 9; ++it) {
        int i = it * 256 + threadIdx.x;
        int L = L0 + i;
        float k  = sp10(src[L]);
        float m1 = src[9 * SP + L];
        float m2 = src[18 * SP + L];
        shk[i] = k; shm1[i] = m1; shm2[i] = m2;
        okap[L] = k;
        om[L] = m1;
        om[9 * SP + L] = m2;
    }
    __syncthreads();
#pragma unroll
    for (int it = 0; it < 9; ++it) {
        int i = it * 256 + threadIdx.x;
        int so = i & 255;
        int t = i >> 8;
        int si = 9 * so + t;
        size_t dst = ((size_t)b * 9 + t) * SP + s0 + so;
        g_kg[dst] = shk[si];
        g_m1[dst] = shm1[si];
        g_m2[dst] = shm2[si];
    }
}

// ---------------------------------------------------------------------------
__global__ void epiH_k(float* __restrict__ out) {
    int gid = blockIdx.x * blockDim.x + threadIdx.x;
    int b = gid >> 16;
    int s = gid & (SP - 1);
    const float* pb = g_p3 + (size_t)b * C3 * SP + s;
    float gm[NT], vx[NT], vy[NT];
#pragma unroll
    for (int t = 0; t < NT; t++) {
        gm[t] = sp10(pb[(size_t)(27 + t) * SP]);
        vx[t] = pb[(size_t)(36 + t) * SP];
        vy[t] = pb[(size_t)(45 + t) * SP];
    }
    const size_t PLANE = (size_t)SP * NT;
    size_t base = OFF_H + (size_t)b * 4 * PLANE + (size_t)s * NT;
#pragma unroll
    for (int t = 0; t < NT; t++) out[base + t] = gm[t] + vx[t] * vx[t];
#pragma unroll
    for (int t = 0; t < NT; t++) {
        float xy = vx[t] * vy[t];
        out[base + PLANE + t]     = xy;
        out[base + 2 * PLANE + t] = xy;
    }
#pragma unroll
    for (int t = 0; t < NT; t++) out[base + 3 * PLANE + t] = gm[t] + vy[t] * vy[t];
}

// ---------------------------------------------------------------------------
__global__ void transpose_k(const float* __restrict__ x) {
    __shared__ float tile[32][33];
    int b = blockIdx.z / NT, t = blockIdx.z % NT;
    const float* xb = x + ((size_t)b * NT + t) * SP;
    float* og = g_xg + ((size_t)b * NT + t) * SP;
    int Y0 = blockIdx.y * 32, X0 = blockIdx.x * 32;
#pragma unroll
    for (int k = 0; k < 4; k++) {
        int row = threadIdx.y + k * 8;
        tile[row][threadIdx.x] = xb[(size_t)(Y0 + row) * NYX + X0 + threadIdx.x];
    }
    __syncthreads();
#pragma unroll
    for (int k = 0; k < 4; k++) {
        int row = threadIdx.y + k * 8;
        og[(size_t)(X0 + row) * NYX + Y0 + threadIdx.x] = tile[threadIdx.x][row];
    }
}

// ---------------------------------------------------------------------------
__global__ void applyM_k(const float* __restrict__ u, float* __restrict__ og) {
    __shared__ float tile[10][36];
    int bt = blockIdx.z;
    int b = bt / NT, t = bt % NT;
    int A0 = blockIdx.y * 8, C0 = blockIdx.x * 32;
    const float* ub = u + (size_t)bt * SP;
    int tid = threadIdx.y * 32 + threadIdx.x;
    for (int i = tid; i < 10 * 34; i += 256) {
        int rr = i / 34, cc = i % 34;
        int A = A0 - 1 + rr, C = C0 - 1 + cc;
        tile[rr][cc] = (A >= 0 && A < NYX && C >= 0 && C < NYX)
                       ? ub[(size_t)A * NYX + C] : 0.0f;
    }
    __syncthreads();
    int a = threadIdx.y, c = threadIdx.x;
    float u0 = tile[a + 1][c + 1];
    float xp = tile[a + 2][c + 1], xm = tile[a][c + 1];
    float yp = tile[a + 1][c + 2], ym = tile[a + 1][c];
    float pp = tile[a + 2][c + 2], pm = tile[a + 2][c];
    float mp = tile[a][c + 2],     mm = tile[a][c];
    float dx  = 0.5f * (xp - xm);
    float dy  = 0.5f * (yp - ym);
    float dxx = xp - 2.0f * u0 + xm;
    float dyy = yp - 2.0f * u0 + ym;
    float dxy = 0.25f * (pp - pm - mp + mm);

    int s = (A0 + a) * NYX + (C0 + c);
    size_t pl = (size_t)bt * SP + s;
    const float* pb = g_p3 + (size_t)b * C3 * SP + s;
    float gm = sp10(pb[(size_t)(27 + t) * SP]);
    float vx = pb[(size_t)(36 + t) * SP];
    float vy = pb[(size_t)(45 + t) * SP];
    float kap = g_kg[pl];
    float m1  = g_m1[pl];
    float m2  = g_m2[pl];

    float r = u0 + kap * kap * u0 + m1 * dx + m2 * dy
            - ((gm + vx * vx) * dxx + 2.0f * vx * vy * dxy + (gm + vy * vy) * dyy);
    og[pl] = r;
}

// ---------------------------------------------------------------------------
__global__ void qx_reduce_k() {
    __shared__ float sm[256];
    int b = blockIdx.y;
    size_t base = (size_t)blockIdx.x * 4096;
    const float* xb = g_xg + (size_t)b * NT * SP;
    const float* wb = g_w  + (size_t)b * NT * SP;
    const float* vb = g_v  + (size_t)b * NT * SP;
    float sum = 0.0f;
    for (int i = threadIdx.x; i < 4096; i += 256) {
        size_t e = base + i;
        int t = (int)(e >> 16);
        int s = (int)(e & (SP - 1));
        float q;
        if (t == 0)       q = vb[s] - wb[SP + s];
        else if (t == 8)  q = -wb[7 * SP + s] + vb[8 * (size_t)SP + s];
        else              q = -wb[(size_t)(t - 1) * SP + s] + vb[e] + xb[e]
                              - wb[(size_t)(t + 1) * SP + s];
        sum += xb[e] * q;
    }
    sm[threadIdx.x] = sum;
    __syncthreads();
    for (int st = 128; st > 0; st >>= 1) {
        if (threadIdx.x < st) sm[threadIdx.x] += sm[threadIdx.x + st];
        __syncthreads();
    }
    if (threadIdx.x == 0) g_part[b * 160 + blockIdx.x] = sm[0];
}

__global__ void final_reduce_k(float* __restrict__ out) {
    int b = threadIdx.x;
    if (b < NB) {
        float s = 0.0f;
        for (int i = 0; i < 144; i++) s += g_part[b * 160 + i];
        out[OFF_XOUT + b] = s;
    }
}

// ---------------------------------------------------------------------------
extern "C" void kernel_launch(void* const* d_in, const int* in_sizes, int n_in,
                              void* d_out, int out_size) {
    const float* x  = (const float*)d_in[0];
    const float* w1 = (const float*)d_in[4];
    const float* w2 = (const float*)d_in[5];
    const float* w3 = (const float*)d_in[6];
    float* out = (float*)d_out;

    float *p1, *p2, *p3, *xg, *wg, *vg;
    cudaGetSymbolAddress((void**)&p1, g_p1);
    cudaGetSymbolAddress((void**)&p2, g_p2);
    cudaGetSymbolAddress((void**)&p3, g_p3);
    cudaGetSymbolAddress((void**)&xg, g_xg);
    cudaGetSymbolAddress((void**)&wg, g_w);
    cudaGetSymbolAddress((void**)&vg, g_v);

    // one-time side stream + events (created on first, non-captured call)
    static cudaStream_t s1 = nullptr;
    static cudaEvent_t ev0 = nullptr, evT = nullptr, evC = nullptr, ev1 = nullptr;
    if (!s1) {
        cudaStreamCreateWithFlags(&s1, cudaStreamNonBlocking);
        cudaEventCreateWithFlags(&ev0, cudaEventDisableTiming);
        cudaEventCreateWithFlags(&evT, cudaEventDisableTiming);
        cudaEventCreateWithFlags(&evC, cudaEventDisableTiming);
        cudaEventCreateWithFlags(&ev1, cudaEventDisableTiming);
    }

    // conv1: MT=1,KS=6,WOFF=0; conv2: MT=2,KS=6,WOFF=6; conv3: MT=2 x 2 chunks,KS=12,WOFF=18
    const int smem1 = (9  * 3 + 1) * TSK * 4 + 6  * 16 * 4;
    const int smem2 = (10 * 3 + 1) * TSK * 4 + 6  * 16 * 4;
    const int smem3 = (20 * 3 + 1) * TSK * 4 + 12 * 16 * 4;
    cudaFuncSetAttribute((const void*)conv_mma_k<9,  true,  1, 6,  C1, 0,  4>, cudaFuncAttributeMaxDynamicSharedMemorySize, smem1);
    cudaFuncSetAttribute((const void*)conv_mma_k<10, true,  2, 6,  C2, 6,  3>, cudaFuncAttributeMaxDynamicSharedMemorySize, smem2);
    cudaFuncSetAttribute((const void*)conv_mma_k<20, false, 2, 12, C3, 18, 3>, cudaFuncAttributeMaxDynamicSharedMemorySize, smem3);

    // fork: transpose on side stream (depends only on x)
    cudaEventRecord(ev0, 0);
    cudaStreamWaitEvent(s1, ev0, 0);
    transpose_k<<<dim3(8, 8, NB * NT), dim3(32, 8), 0, s1>>>(x);
    cudaEventRecord(evT, s1);

    // main stream: conv chain
    prep_w_k<<<9, 256>>>(w1, w2, w3);
    conv_mma_k<9,  true,  1, 6,  C1, 0,  4><<<dim3(1, 256, NB), dim3(32, 8), smem1>>>(x,  p1);
    conv_mma_k<10, true,  2, 6,  C2, 6,  3><<<dim3(1, 256, NB), dim3(32, 8), smem2>>>(p1, p2);
    conv_mma_k<20, false, 2, 12, C3, 18, 3><<<dim3(2, 256, NB), dim3(32, 8), smem3>>>(p2, p3);
    cudaEventRecord(evC, 0);

    // side stream: epiH (depends on conv3 only)
    cudaStreamWaitEvent(s1, evC, 0);
    epiH_k<<<(NB * SP) / 256, 256, 0, s1>>>(out);
    cudaEventRecord(ev1, s1);

    // main stream: epiA -> PDE pipeline
    epiA_scramble_k<<<dim3(256, NB), 256>>>(out);
    cudaStreamWaitEvent(0, evT, 0);
    applyM_k<<<dim3(8, 32, NB * NT), dim3(32, 8)>>>(xg, wg);
    applyM_k<<<dim3(8, 32, NB * NT), dim3(32, 8)>>>(wg, vg);
    qx_reduce_k<<<dim3(144, NB), 256>>>();
    cudaStreamWaitEvent(0, ev1, 0);
    final_reduce_k<<<1, 32>>>(out);
}

// round 13
// speedup vs baseline: 1.0780x; 1.0780x over previous
#include <cuda_runtime.h>
#include <cuda_bf16.h>
#include <cstdint>

#define NB 16
#define NT 9
#define NYX 256
#define SP 65536
#define C1 10
#define C2 20
#define C3 54

#define OFF_XOUT 0
#define OFF_KAP  16
#define OFF_M    9437200
#define OFF_H    28311568

#define TSK 288   // skewed tile row stride

__device__ float g_p1[NB * C1 * SP];
__device__ float g_p2[NB * C2 * SP];
__device__ float g_p3[NB * C3 * SP];
__device__ float g_xg[NB * NT * SP];
__device__ float g_w [NB * NT * SP];
__device__ float g_v [NB * NT * SP];
__device__ float g_kg [NB * NT * SP];
__device__ float g_m1 [NB * NT * SP];
__device__ float g_m2 [NB * NT * SP];
__device__ float g_part[NB * 160];
// bf16 A-fragments: conv1 slots 0..5 (MT1,KS6); conv2 6..17 (MT2,KS6);
// conv3 18..65 (4 m-tiles x KS12).
__device__ uint4 g_wfrag[66 * 32 * 2];

__device__ __forceinline__ float sp10(float x) {
    float z = 10.0f * x;
    return (fmaxf(z, 0.0f) + log1pf(expf(-fabsf(z)))) * 0.1f;
}
__device__ __forceinline__ uint32_t bfpack(float lo, float hi) {
    uint32_t r; asm("cvt.rn.bf16x2.f32 %0, %1, %2;" : "=r"(r) : "f"(hi), "f"(lo));
    return r;
}
__device__ __forceinline__ float bf_lo(uint32_t h) { return __uint_as_float(h << 16); }
__device__ __forceinline__ float bf_hi(uint32_t h) { return __uint_as_float(h & 0xFFFF0000u); }

__device__ __forceinline__ void mma_bf16(float* d, const uint32_t* a, const uint32_t* b) {
    asm("mma.sync.aligned.m16n8k16.row.col.f32.bf16.bf16.f32 "
        "{%0,%1,%2,%3}, {%4,%5,%6,%7}, {%8,%9}, {%0,%1,%2,%3};"
        : "+f"(d[0]), "+f"(d[1]), "+f"(d[2]), "+f"(d[3])
        : "r"(a[0]), "r"(a[1]), "r"(a[2]), "r"(a[3]), "r"(b[0]), "r"(b[1]));
}

// ---------------------------------------------------------------------------
__global__ void prep_w_k(const float* __restrict__ w1,
                         const float* __restrict__ w2,
                         const float* __restrict__ w3) {
    int idx = blockIdx.x * blockDim.x + threadIdx.x;
    if (idx >= 66 * 32) return;
    int lane = idx & 31;
    int slot = idx >> 5;
    const float* w; int K, COUT, mt, ks;
    if (slot < 6)       { w = w1; K = 81;  COUT = C1; mt = 0;               ks = slot; }
    else if (slot < 18) { w = w2; K = 90;  COUT = C2; int s = slot - 6;  mt = s / 6;  ks = s % 6; }
    else                { w = w3; K = 180; COUT = C3; int s = slot - 18; mt = s / 12; ks = s % 12; }
    int g = lane >> 2, tig = lane & 3;
    uint32_t hi[4], lo[4];
#pragma unroll
    for (int i = 0; i < 4; i++) {
        int row = mt * 16 + g + (i & 1) * 8;
        int k   = ks * 16 + (i >> 1) * 8 + 2 * tig;
        float w0 = (row < COUT && k     < K) ? w[row * K + k]     : 0.0f;
        float w1v = (row < COUT && k + 1 < K) ? w[row * K + k + 1] : 0.0f;
        uint32_t h = bfpack(w0, w1v);
        hi[i] = h;
        lo[i] = bfpack(w0 - bf_lo(h), w1v - bf_hi(h));
    }
    int base = (slot * 32 + lane) * 2;
    g_wfrag[base]     = make_uint4(hi[0], hi[1], hi[2], hi[3]);
    g_wfrag[base + 1] = make_uint4(lo[0], lo[1], lo[2], lo[3]);
}

// ---------------------------------------------------------------------------
// Generic conv3x3, bf16 m16n8k16 3-pass, one output row per block.
// ---------------------------------------------------------------------------
template <int CIN, bool RELU_IN, int MT, int KS, int COUT, int WOFF, int MAXB>
__global__ void __launch_bounds__(256, MAXB)
conv_mma_k(const float* __restrict__ in, float* __restrict__ out) {
    extern __shared__ float sh[];
    const int ZR = CIN * 3;
    float* tile = sh;
    int*   koff = (int*)(sh + (ZR + 1) * TSK);

    const int b  = blockIdx.z;
    const int y0 = blockIdx.y;
    const int tid = threadIdx.y * 32 + threadIdx.x;

    const float* inb = in + (size_t)b * CIN * SP;
    for (int idx = tid; idx < CIN * 3 * 258; idx += 256) {
        int c  = idx % 258;
        int rr = (idx / 258) % 3;
        int ci = idx / 774;
        int gy = y0 - 1 + rr;
        int gx = c - 1;
        float v = 0.0f;
        if (gy >= 0 && gy < NYX && gx >= 0 && gx < NYX) {
            v = inb[ci * SP + gy * NYX + gx];
            if (RELU_IN) v = fmaxf(v, 0.0f);
        }
        tile[(ci * 3 + rr) * TSK + 8 * rr + c] = v;
    }
    for (int i = tid; i < TSK; i += 256) tile[ZR * TSK + i] = 0.0f;
    for (int k = tid; k < KS * 16; k += 256) {
        if (k < CIN * 9) {
            int ci = k / 9, r = k % 9;
            int ky = r / 3;
            koff[k] = (ci * 3 + ky) * TSK + 8 * ky + (r % 3);
        } else {
            koff[k] = ZR * TSK;
        }
    }
    __syncthreads();

    const int warp = threadIdx.y;
    const int lane = threadIdx.x;
    const int g = lane >> 2, tig = lane & 3;
    const int nbase = warp * 32;

    float acc[MT][4][4];
#pragma unroll
    for (int m = 0; m < MT; m++)
#pragma unroll
        for (int n = 0; n < 4; n++)
#pragma unroll
            for (int q = 0; q < 4; q++) acc[m][n][q] = 0.0f;

    for (int ks = 0; ks < KS; ks++) {
        int o00 = koff[ks * 16 + 2 * tig];
        int o01 = koff[ks * 16 + 2 * tig + 1];
        int o10 = koff[ks * 16 + 8 + 2 * tig];
        int o11 = koff[ks * 16 + 8 + 2 * tig + 1];
        uint32_t bhi[4][2], blo[4][2];
#pragma unroll
        for (int nt = 0; nt < 4; nt++) {
            int n = nbase + nt * 8 + g;
            float x00 = tile[o00 + n], x01 = tile[o01 + n];
            float x10 = tile[o10 + n], x11 = tile[o11 + n];
            uint32_t h0 = bfpack(x00, x01);
            uint32_t h1 = bfpack(x10, x11);
            bhi[nt][0] = h0;
            bhi[nt][1] = h1;
            blo[nt][0] = bfpack(x00 - bf_lo(h0), x01 - bf_hi(h0));
            blo[nt][1] = bfpack(x10 - bf_lo(h1), x11 - bf_hi(h1));
        }
#pragma unroll
        for (int mt = 0; mt < MT; mt++) {
            int base = ((WOFF + mt * KS + ks) * 32 + lane) * 2;
            uint4 ah = g_wfrag[base];
            uint4 al = g_wfrag[base + 1];
            uint32_t ahi[4] = { ah.x, ah.y, ah.z, ah.w };
            uint32_t alo[4] = { al.x, al.y, al.z, al.w };
#pragma unroll
            for (int nt = 0; nt < 4; nt++) {
                mma_bf16(acc[mt][nt], ahi, bhi[nt]);
                mma_bf16(acc[mt][nt], ahi, blo[nt]);
                mma_bf16(acc[mt][nt], alo, bhi[nt]);
            }
        }
    }

#pragma unroll
    for (int mt = 0; mt < MT; mt++) {
        int co0 = mt * 16 + g;
#pragma unroll
        for (int nt = 0; nt < 4; nt++) {
            int px = nbase + nt * 8 + 2 * tig;
            float* op = out + ((size_t)b * COUT + co0) * SP + (size_t)y0 * NYX + px;
            if (co0 < COUT)
                *reinterpret_cast<float2*>(op) = make_float2(acc[mt][nt][0], acc[mt][nt][1]);
            if (co0 + 8 < COUT)
                *reinterpret_cast<float2*>(op + (size_t)8 * SP) = make_float2(acc[mt][nt][2], acc[mt][nt][3]);
        }
    }
}

// ---------------------------------------------------------------------------
__global__ void epiA_scramble_k(float* __restrict__ out) {
    __shared__ float shk[2304], shm1[2304], shm2[2304];
    int b = blockIdx.y;
    int chunk = blockIdx.x;
    int L0 = chunk * 2304;
    int s0 = chunk * 256;
    const float* src = g_p3 + (size_t)b * C3 * SP;
    float* okap = out + OFF_KAP + (size_t)b * 9 * SP;
    float* om   = out + OFF_M   + (size_t)b * 18 * SP;
#pragma unroll
    for (int it = 0; it < 9; ++it) {
        int i = it * 256 + threadIdx.x;
        int L = L0 + i;
        float k  = sp10(src[L]);
        float m1 = src[9 * SP + L];
        float m2 = src[18 * SP + L];
        shk[i] = k; shm1[i] = m1; shm2[i] = m2;
        okap[L] = k;
        om[L] = m1;
        om[9 * SP + L] = m2;
    }
    __syncthreads();
#pragma unroll
    for (int it = 0; it < 9; ++it) {
        int i = it * 256 + threadIdx.x;
        int so = i & 255;
        int t = i >> 8;
        int si = 9 * so + t;
        size_t dst = ((size_t)b * 9 + t) * SP + s0 + so;
        g_kg[dst] = shk[si];
        g_m1[dst] = shm1[si];
        g_m2[dst] = shm2[si];
    }
}

// ---------------------------------------------------------------------------
__global__ void epiH_k(float* __restrict__ out) {
    int gid = blockIdx.x * blockDim.x + threadIdx.x;
    int b = gid >> 16;
    int s = gid & (SP - 1);
    const float* pb = g_p3 + (size_t)b * C3 * SP + s;
    float gm[NT], vx[NT], vy[NT];
#pragma unroll
    for (int t = 0; t < NT; t++) {
        gm[t] = sp10(pb[(size_t)(27 + t) * SP]);
        vx[t] = pb[(size_t)(36 + t) * SP];
        vy[t] = pb[(size_t)(45 + t) * SP];
    }
    const size_t PLANE = (size_t)SP * NT;
    size_t base = OFF_H + (size_t)b * 4 * PLANE + (size_t)s * NT;
#pragma unroll
    for (int t = 0; t < NT; t++) out[base + t] = gm[t] + vx[t] * vx[t];
#pragma unroll
    for (int t = 0; t < NT; t++) {
        float xy = vx[t] * vy[t];
        out[base + PLANE + t]     = xy;
        out[base + 2 * PLANE + t] = xy;
    }
#pragma unroll
    for (int t = 0; t < NT; t++) out[base + 3 * PLANE + t] = gm[t] + vy[t] * vy[t];
}

// ---------------------------------------------------------------------------
__global__ void transpose_k(const float* __restrict__ x) {
    __shared__ float tile[32][33];
    int b = blockIdx.z / NT, t = blockIdx.z % NT;
    const float* xb = x + ((size_t)b * NT + t) * SP;
    float* og = g_xg + ((size_t)b * NT + t) * SP;
    int Y0 = blockIdx.y * 32, X0 = blockIdx.x * 32;
#pragma unroll
    for (int k = 0; k < 4; k++) {
        int row = threadIdx.y + k * 8;
        tile[row][threadIdx.x] = xb[(size_t)(Y0 + row) * NYX + X0 + threadIdx.x];
    }
    __syncthreads();
#pragma unroll
    for (int k = 0; k < 4; k++) {
        int row = threadIdx.y + k * 8;
        og[(size_t)(X0 + row) * NYX + Y0 + threadIdx.x] = tile[threadIdx.x][row];
    }
}

// ---------------------------------------------------------------------------
__global__ void applyM_k(const float* __restrict__ u, float* __restrict__ og) {
    __shared__ float tile[10][36];
    int bt = blockIdx.z;
    int b = bt / NT, t = bt % NT;
    int A0 = blockIdx.y * 8, C0 = blockIdx.x * 32;
    const float* ub = u + (size_t)bt * SP;
    int tid = threadIdx.y * 32 + threadIdx.x;
    for (int i = tid; i < 10 * 34; i += 256) {
        int rr = i / 34, cc = i % 34;
        int A = A0 - 1 + rr, C = C0 - 1 + cc;
        tile[rr][cc] = (A >= 0 && A < NYX && C >= 0 && C < NYX)
                       ? ub[(size_t)A * NYX + C] : 0.0f;
    }
    __syncthreads();
    int a = threadIdx.y, c = threadIdx.x;
    float u0 = tile[a + 1][c + 1];
    float xp = tile[a + 2][c + 1], xm = tile[a][c + 1];
    float yp = tile[a + 1][c + 2], ym = tile[a + 1][c];
    float pp = tile[a + 2][c + 2], pm = tile[a + 2][c];
    float mp = tile[a][c + 2],     mm = tile[a][c];
    float dx  = 0.5f * (xp - xm);
    float dy  = 0.5f * (yp - ym);
    float dxx = xp - 2.0f * u0 + xm;
    float dyy = yp - 2.0f * u0 + ym;
    float dxy = 0.25f * (pp - pm - mp + mm);

    int s = (A0 + a) * NYX + (C0 + c);
    size_t pl = (size_t)bt * SP + s;
    const float* pb = g_p3 + (size_t)b * C3 * SP + s;
    float gm = sp10(pb[(size_t)(27 + t) * SP]);
    float vx = pb[(size_t)(36 + t) * SP];
    float vy = pb[(size_t)(45 + t) * SP];
    float kap = g_kg[pl];
    float m1  = g_m1[pl];
    float m2  = g_m2[pl];

    float r = u0 + kap * kap * u0 + m1 * dx + m2 * dy
            - ((gm + vx * vx) * dxx + 2.0f * vx * vy * dxy + (gm + vy * vy) * dyy);
    og[pl] = r;
}

// ---------------------------------------------------------------------------
__global__ void qx_reduce_k() {
    __shared__ float sm[256];
    int b = blockIdx.y;
    size_t base = (size_t)blockIdx.x * 4096;
    const float* xb = g_xg + (size_t)b * NT * SP;
    const float* wb = g_w  + (size_t)b * NT * SP;
    const float* vb = g_v  + (size_t)b * NT * SP;
    float sum = 0.0f;
    for (int i = threadIdx.x; i < 4096; i += 256) {
        size_t e = base + i;
        int t = (int)(e >> 16);
        int s = (int)(e & (SP - 1));
        float q;
        if (t == 0)       q = vb[s] - wb[SP + s];
        else if (t == 8)  q = -wb[7 * SP + s] + vb[8 * (size_t)SP + s];
        else              q = -wb[(size_t)(t - 1) * SP + s] + vb[e] + xb[e]
                              - wb[(size_t)(t + 1) * SP + s];
        sum += xb[e] * q;
    }
    sm[threadIdx.x] = sum;
    __syncthreads();
    for (int st = 128; st > 0; st >>= 1) {
        if (threadIdx.x < st) sm[threadIdx.x] += sm[threadIdx.x + st];
        __syncthreads();
    }
    if (threadIdx.x == 0) g_part[b * 160 + blockIdx.x] = sm[0];
}

__global__ void final_reduce_k(float* __restrict__ out) {
    int b = threadIdx.x;
    if (b < NB) {
        float s = 0.0f;
        for (int i = 0; i < 144; i++) s += g_part[b * 160 + i];
        out[OFF_XOUT + b] = s;
    }
}

// ---------------------------------------------------------------------------
extern "C" void kernel_launch(void* const* d_in, const int* in_sizes, int n_in,
                              void* d_out, int out_size) {
    const float* x  = (const float*)d_in[0];
    const float* w1 = (const float*)d_in[4];
    const float* w2 = (const float*)d_in[5];
    const float* w3 = (const float*)d_in[6];
    float* out = (float*)d_out;

    float *p1, *p2, *p3, *xg, *wg, *vg;
    cudaGetSymbolAddress((void**)&p1, g_p1);
    cudaGetSymbolAddress((void**)&p2, g_p2);
    cudaGetSymbolAddress((void**)&p3, g_p3);
    cudaGetSymbolAddress((void**)&xg, g_xg);
    cudaGetSymbolAddress((void**)&wg, g_w);
    cudaGetSymbolAddress((void**)&vg, g_v);

    // one-time side stream + events (created on first, non-captured call)
    static cudaStream_t s1 = nullptr;
    static cudaEvent_t ev0 = nullptr, evT = nullptr, evC = nullptr, ev1 = nullptr;
    if (!s1) {
        cudaStreamCreateWithFlags(&s1, cudaStreamNonBlocking);
        cudaEventCreateWithFlags(&ev0, cudaEventDisableTiming);
        cudaEventCreateWithFlags(&evT, cudaEventDisableTiming);
        cudaEventCreateWithFlags(&evC, cudaEventDisableTiming);
        cudaEventCreateWithFlags(&ev1, cudaEventDisableTiming);
    }

    // conv1: MT=1,KS=6,WOFF=0; conv2: MT=2,KS=6,WOFF=6; conv3: MT=4,KS=12,WOFF=18
    const int smem1 = (9  * 3 + 1) * TSK * 4 + 6  * 16 * 4;
    const int smem2 = (10 * 3 + 1) * TSK * 4 + 6  * 16 * 4;
    const int smem3 = (20 * 3 + 1) * TSK * 4 + 12 * 16 * 4;
    cudaFuncSetAttribute((const void*)conv_mma_k<9,  true,  1, 6,  C1, 0,  4>, cudaFuncAttributeMaxDynamicSharedMemorySize, smem1);
    cudaFuncSetAttribute((const void*)conv_mma_k<10, true,  2, 6,  C2, 6,  3>, cudaFuncAttributeMaxDynamicSharedMemorySize, smem2);
    cudaFuncSetAttribute((const void*)conv_mma_k<20, false, 4, 12, C3, 18, 2>, cudaFuncAttributeMaxDynamicSharedMemorySize, smem3);

    // fork: transpose on side stream (depends only on x)
    cudaEventRecord(ev0, 0);
    cudaStreamWaitEvent(s1, ev0, 0);
    transpose_k<<<dim3(8, 8, NB * NT), dim3(32, 8), 0, s1>>>(x);
    cudaEventRecord(evT, s1);

    // main stream: conv chain
    prep_w_k<<<9, 256>>>(w1, w2, w3);
    conv_mma_k<9,  true,  1, 6,  C1, 0,  4><<<dim3(1, 256, NB), dim3(32, 8), smem1>>>(x,  p1);
    conv_mma_k<10, true,  2, 6,  C2, 6,  3><<<dim3(1, 256, NB), dim3(32, 8), smem2>>>(p1, p2);
    conv_mma_k<20, false, 4, 12, C3, 18, 2><<<dim3(1, 256, NB), dim3(32, 8), smem3>>>(p2, p3);
    cudaEventRecord(evC, 0);

    // side stream: epiH (depends on conv3 only)
    cudaStreamWaitEvent(s1, evC, 0);
    epiH_k<<<(NB * SP) / 256, 256, 0, s1>>>(out);
    cudaEventRecord(ev1, s1);

    // main stream: epiA -> PDE pipeline
    epiA_scramble_k<<<dim3(256, NB), 256>>>(out);
    cudaStreamWaitEvent(0, evT, 0);
    applyM_k<<<dim3(8, 32, NB * NT), dim3(32, 8)>>>(xg, wg);
    applyM_k<<<dim3(8, 32, NB * NT), dim3(32, 8)>>>(wg, vg);
    qx_reduce_k<<<dim3(144, NB), 256>>>();
    cudaStreamWaitEvent(0, ev1, 0);
    final_reduce_k<<<1, 32>>>(out);
}

// round 14
// speedup vs baseline: 1.0942x; 1.0150x over previous
#include <cuda_runtime.h>
#include <cuda_bf16.h>
#include <cstdint>

#define NB 16
#define NT 9
#define NYX 256
#define SP 65536
#define C1 10
#define C2 20
#define C3 54

#define OFF_XOUT 0
#define OFF_KAP  16
#define OFF_M    9437200
#define OFF_H    28311568

#define TSK 288   // skewed tile row stride
#define NPART 2304  // partial sums per batch (8*32*9 blocks)

__device__ float g_p1[NB * C1 * SP];
__device__ float g_p2[NB * C2 * SP];
__device__ float g_p3[NB * C3 * SP];
__device__ float g_xg[NB * NT * SP];
__device__ float g_w [NB * NT * SP];
__device__ float g_kg [NB * NT * SP];
__device__ float g_m1 [NB * NT * SP];
__device__ float g_m2 [NB * NT * SP];
__device__ float g_part[NB * NPART];
// A-fragments (hi,lo uint4 pairs): conv1 slots 0..5 (MT1,KS6, fp16);
// conv2 6..17 (MT2,KS6, fp16); conv3 18..65 (MT4,KS12, bf16).
__device__ uint4 g_wfrag[66 * 32 * 2];

__device__ __forceinline__ float sp10(float x) {
    float z = 10.0f * x;
    return (fmaxf(z, 0.0f) + log1pf(expf(-fabsf(z)))) * 0.1f;
}
// pack (lo, hi) f32 -> bf16x2 / f16x2 (lo in low half)
__device__ __forceinline__ uint32_t bfpack(float lo, float hi) {
    uint32_t r; asm("cvt.rn.bf16x2.f32 %0, %1, %2;" : "=r"(r) : "f"(hi), "f"(lo));
    return r;
}
__device__ __forceinline__ uint32_t hfpack(float lo, float hi) {
    uint32_t r; asm("cvt.rn.f16x2.f32 %0, %1, %2;" : "=r"(r) : "f"(hi), "f"(lo));
    return r;
}
__device__ __forceinline__ float bf_lo(uint32_t h) { return __uint_as_float(h << 16); }
__device__ __forceinline__ float bf_hi(uint32_t h) { return __uint_as_float(h & 0xFFFF0000u); }

__device__ __forceinline__ void mma_bf16(float* d, const uint32_t* a, const uint32_t* b) {
    asm("mma.sync.aligned.m16n8k16.row.col.f32.bf16.bf16.f32 "
        "{%0,%1,%2,%3}, {%4,%5,%6,%7}, {%8,%9}, {%0,%1,%2,%3};"
        : "+f"(d[0]), "+f"(d[1]), "+f"(d[2]), "+f"(d[3])
        : "r"(a[0]), "r"(a[1]), "r"(a[2]), "r"(a[3]), "r"(b[0]), "r"(b[1]));
}
__device__ __forceinline__ void mma_f16(float* d, const uint32_t* a, const uint32_t* b) {
    asm("mma.sync.aligned.m16n8k16.row.col.f32.f16.f16.f32 "
        "{%0,%1,%2,%3}, {%4,%5,%6,%7}, {%8,%9}, {%0,%1,%2,%3};"
        : "+f"(d[0]), "+f"(d[1]), "+f"(d[2]), "+f"(d[3])
        : "r"(a[0]), "r"(a[1]), "r"(a[2]), "r"(a[3]), "r"(b[0]), "r"(b[1]));
}

// ---------------------------------------------------------------------------
// Prep: weights -> A-fragments. conv1/conv2 fp16 hi/lo, conv3 bf16 hi/lo.
// ---------------------------------------------------------------------------
__global__ void prep_w_k(const float* __restrict__ w1,
                         const float* __restrict__ w2,
                         const float* __restrict__ w3) {
    int idx = blockIdx.x * blockDim.x + threadIdx.x;
    if (idx >= 66 * 32) return;
    int lane = idx & 31;
    int slot = idx >> 5;
    const float* w; int K, COUT, mt, ks; bool f16;
    if (slot < 6)       { w = w1; K = 81;  COUT = C1; mt = 0;               ks = slot;  f16 = true; }
    else if (slot < 18) { w = w2; K = 90;  COUT = C2; int s = slot - 6;  mt = s / 6;  ks = s % 6;  f16 = true; }
    else                { w = w3; K = 180; COUT = C3; int s = slot - 18; mt = s / 12; ks = s % 12; f16 = false; }
    int g = lane >> 2, tig = lane & 3;
    uint32_t hi[4], lo[4];
#pragma unroll
    for (int i = 0; i < 4; i++) {
        int row = mt * 16 + g + (i & 1) * 8;
        int k   = ks * 16 + (i >> 1) * 8 + 2 * tig;
        float w0 = (row < COUT && k     < K) ? w[row * K + k]     : 0.0f;
        float w1v = (row < COUT && k + 1 < K) ? w[row * K + k + 1] : 0.0f;
        if (f16) {
            float h0 = __half2float(__float2half_rn(w0));
            float h1 = __half2float(__float2half_rn(w1v));
            hi[i] = hfpack(h0, h1);
            lo[i] = hfpack(w0 - h0, w1v - h1);
        } else {
            uint32_t h = bfpack(w0, w1v);
            hi[i] = h;
            lo[i] = bfpack(w0 - bf_lo(h), w1v - bf_hi(h));
        }
    }
    int base = (slot * 32 + lane) * 2;
    g_wfrag[base]     = make_uint4(hi[0], hi[1], hi[2], hi[3]);
    g_wfrag[base + 1] = make_uint4(lo[0], lo[1], lo[2], lo[3]);
}

// ---------------------------------------------------------------------------
// Shared tile fill for conv kernels (skewed layout).
// ---------------------------------------------------------------------------
template <int CIN, bool RELU_IN, int KS>
__device__ __forceinline__ void conv_fill(const float* __restrict__ in,
                                          float* tile, int* koff,
                                          int b, int y0, int tid) {
    const int ZR = CIN * 3;
    const float* inb = in + (size_t)b * CIN * SP;
    for (int idx = tid; idx < CIN * 3 * 258; idx += 256) {
        int c  = idx % 258;
        int rr = (idx / 258) % 3;
        int ci = idx / 774;
        int gy = y0 - 1 + rr;
        int gx = c - 1;
        float v = 0.0f;
        if (gy >= 0 && gy < NYX && gx >= 0 && gx < NYX) {
            v = inb[ci * SP + gy * NYX + gx];
            if (RELU_IN) v = fmaxf(v, 0.0f);
        }
        tile[(ci * 3 + rr) * TSK + 8 * rr + c] = v;
    }
    for (int i = tid; i < TSK; i += 256) tile[ZR * TSK + i] = 0.0f;
    for (int k = tid; k < KS * 16; k += 256) {
        if (k < CIN * 9) {
            int ci = k / 9, r = k % 9;
            int ky = r / 3;
            koff[k] = (ci * 3 + ky) * TSK + 8 * ky + (r % 3);
        } else {
            koff[k] = ZR * TSK;
        }
    }
}

// ---------------------------------------------------------------------------
// conv3: bf16 m16n8k16 3-pass (hi/lo on both sides).
// ---------------------------------------------------------------------------
template <int CIN, bool RELU_IN, int MT, int KS, int COUT, int WOFF, int MAXB>
__global__ void __launch_bounds__(256, MAXB)
conv_mma_bf16_k(const float* __restrict__ in, float* __restrict__ out) {
    extern __shared__ float sh[];
    float* tile = sh;
    int*   koff = (int*)(sh + (CIN * 3 + 1) * TSK);
    const int b  = blockIdx.z;
    const int y0 = blockIdx.y;
    const int tid = threadIdx.y * 32 + threadIdx.x;
    conv_fill<CIN, RELU_IN, KS>(in, tile, koff, b, y0, tid);
    __syncthreads();

    const int warp = threadIdx.y;
    const int lane = threadIdx.x;
    const int g = lane >> 2, tig = lane & 3;
    const int nbase = warp * 32;

    float acc[MT][4][4];
#pragma unroll
    for (int m = 0; m < MT; m++)
#pragma unroll
        for (int n = 0; n < 4; n++)
#pragma unroll
            for (int q = 0; q < 4; q++) acc[m][n][q] = 0.0f;

    for (int ks = 0; ks < KS; ks++) {
        int o00 = koff[ks * 16 + 2 * tig];
        int o01 = koff[ks * 16 + 2 * tig + 1];
        int o10 = koff[ks * 16 + 8 + 2 * tig];
        int o11 = koff[ks * 16 + 8 + 2 * tig + 1];
        uint32_t bhi[4][2], blo[4][2];
#pragma unroll
        for (int nt = 0; nt < 4; nt++) {
            int n = nbase + nt * 8 + g;
            float x00 = tile[o00 + n], x01 = tile[o01 + n];
            float x10 = tile[o10 + n], x11 = tile[o11 + n];
            uint32_t h0 = bfpack(x00, x01);
            uint32_t h1 = bfpack(x10, x11);
            bhi[nt][0] = h0;
            bhi[nt][1] = h1;
            blo[nt][0] = bfpack(x00 - bf_lo(h0), x01 - bf_hi(h0));
            blo[nt][1] = bfpack(x10 - bf_lo(h1), x11 - bf_hi(h1));
        }
#pragma unroll
        for (int mt = 0; mt < MT; mt++) {
            int base = ((WOFF + mt * KS + ks) * 32 + lane) * 2;
            uint4 ah = g_wfrag[base];
            uint4 al = g_wfrag[base + 1];
            uint32_t ahi[4] = { ah.x, ah.y, ah.z, ah.w };
            uint32_t alo[4] = { al.x, al.y, al.z, al.w };
#pragma unroll
            for (int nt = 0; nt < 4; nt++) {
                mma_bf16(acc[mt][nt], ahi, bhi[nt]);
                mma_bf16(acc[mt][nt], ahi, blo[nt]);
                mma_bf16(acc[mt][nt], alo, bhi[nt]);
            }
        }
    }

#pragma unroll
    for (int mt = 0; mt < MT; mt++) {
        int co0 = mt * 16 + g;
#pragma unroll
        for (int nt = 0; nt < 4; nt++) {
            int px = nbase + nt * 8 + 2 * tig;
            float* op = out + ((size_t)b * COUT + co0) * SP + (size_t)y0 * NYX + px;
            if (co0 < COUT)
                *reinterpret_cast<float2*>(op) = make_float2(acc[mt][nt][0], acc[mt][nt][1]);
            if (co0 + 8 < COUT)
                *reinterpret_cast<float2*>(op + (size_t)8 * SP) = make_float2(acc[mt][nt][2], acc[mt][nt][3]);
        }
    }
}

// ---------------------------------------------------------------------------
// conv1/conv2: fp16 2-pass (weights hi/lo fp16, image single fp16).
// ---------------------------------------------------------------------------
template <int CIN, bool RELU_IN, int MT, int KS, int COUT, int WOFF, int MAXB>
__global__ void __launch_bounds__(256, MAXB)
conv_mma_f16_k(const float* __restrict__ in, float* __restrict__ out) {
    extern __shared__ float sh[];
    float* tile = sh;
    int*   koff = (int*)(sh + (CIN * 3 + 1) * TSK);
    const int b  = blockIdx.z;
    const int y0 = blockIdx.y;
    const int tid = threadIdx.y * 32 + threadIdx.x;
    conv_fill<CIN, RELU_IN, KS>(in, tile, koff, b, y0, tid);
    __syncthreads();

    const int warp = threadIdx.y;
    const int lane = threadIdx.x;
    const int g = lane >> 2, tig = lane & 3;
    const int nbase = warp * 32;

    float acc[MT][4][4];
#pragma unroll
    for (int m = 0; m < MT; m++)
#pragma unroll
        for (int n = 0; n < 4; n++)
#pragma unroll
            for (int q = 0; q < 4; q++) acc[m][n][q] = 0.0f;

    for (int ks = 0; ks < KS; ks++) {
        int o00 = koff[ks * 16 + 2 * tig];
        int o01 = koff[ks * 16 + 2 * tig + 1];
        int o10 = koff[ks * 16 + 8 + 2 * tig];
        int o11 = koff[ks * 16 + 8 + 2 * tig + 1];
        uint32_t bfr[4][2];
#pragma unroll
        for (int nt = 0; nt < 4; nt++) {
            int n = nbase + nt * 8 + g;
            bfr[nt][0] = hfpack(tile[o00 + n], tile[o01 + n]);
            bfr[nt][1] = hfpack(tile[o10 + n], tile[o11 + n]);
        }
#pragma unroll
        for (int mt = 0; mt < MT; mt++) {
            int base = ((WOFF + mt * KS + ks) * 32 + lane) * 2;
            uint4 ah = g_wfrag[base];
            uint4 al = g_wfrag[base + 1];
            uint32_t ahi[4] = { ah.x, ah.y, ah.z, ah.w };
            uint32_t alo[4] = { al.x, al.y, al.z, al.w };
#pragma unroll
            for (int nt = 0; nt < 4; nt++) {
                mma_f16(acc[mt][nt], ahi, bfr[nt]);
                mma_f16(acc[mt][nt], alo, bfr[nt]);
            }
        }
    }

#pragma unroll
    for (int mt = 0; mt < MT; mt++) {
        int co0 = mt * 16 + g;
#pragma unroll
        for (int nt = 0; nt < 4; nt++) {
            int px = nbase + nt * 8 + 2 * tig;
            float* op = out + ((size_t)b * COUT + co0) * SP + (size_t)y0 * NYX + px;
            if (co0 < COUT)
                *reinterpret_cast<float2*>(op) = make_float2(acc[mt][nt][0], acc[mt][nt][1]);
            if (co0 + 8 < COUT)
                *reinterpret_cast<float2*>(op + (size_t)8 * SP) = make_float2(acc[mt][nt][2], acc[mt][nt][3]);
        }
    }
}

// ---------------------------------------------------------------------------
__global__ void epiA_scramble_k(float* __restrict__ out) {
    __shared__ float shk[2304], shm1[2304], shm2[2304];
    int b = blockIdx.y;
    int chunk = blockIdx.x;
    int L0 = chunk * 2304;
    int s0 = chunk * 256;
    const float* src = g_p3 + (size_t)b * C3 * SP;
    float* okap = out + OFF_KAP + (size_t)b * 9 * SP;
    float* om   = out + OFF_M   + (size_t)b * 18 * SP;
#pragma unroll
    for (int it = 0; it < 9; ++it) {
        int i = it * 256 + threadIdx.x;
        int L = L0 + i;
        float k  = sp10(src[L]);
        float m1 = src[9 * SP + L];
        float m2 = src[18 * SP + L];
        shk[i] = k; shm1[i] = m1; shm2[i] = m2;
        okap[L] = k;
        om[L] = m1;
        om[9 * SP + L] = m2;
    }
    __syncthreads();
#pragma unroll
    for (int it = 0; it < 9; ++it) {
        int i = it * 256 + threadIdx.x;
        int so = i & 255;
        int t = i >> 8;
        int si = 9 * so + t;
        size_t dst = ((size_t)b * 9 + t) * SP + s0 + so;
        g_kg[dst] = shk[si];
        g_m1[dst] = shm1[si];
        g_m2[dst] = shm2[si];
    }
}

// ---------------------------------------------------------------------------
__global__ void epiH_k(float* __restrict__ out) {
    int gid = blockIdx.x * blockDim.x + threadIdx.x;
    int b = gid >> 16;
    int s = gid & (SP - 1);
    const float* pb = g_p3 + (size_t)b * C3 * SP + s;
    float gm[NT], vx[NT], vy[NT];
#pragma unroll
    for (int t = 0; t < NT; t++) {
        gm[t] = sp10(pb[(size_t)(27 + t) * SP]);
        vx[t] = pb[(size_t)(36 + t) * SP];
        vy[t] = pb[(size_t)(45 + t) * SP];
    }
    const size_t PLANE = (size_t)SP * NT;
    size_t base = OFF_H + (size_t)b * 4 * PLANE + (size_t)s * NT;
#pragma unroll
    for (int t = 0; t < NT; t++) out[base + t] = gm[t] + vx[t] * vx[t];
#pragma unroll
    for (int t = 0; t < NT; t++) {
        float xy = vx[t] * vy[t];
        out[base + PLANE + t]     = xy;
        out[base + 2 * PLANE + t] = xy;
    }
#pragma unroll
    for (int t = 0; t < NT; t++) out[base + 3 * PLANE + t] = gm[t] + vy[t] * vy[t];
}

// ---------------------------------------------------------------------------
__global__ void transpose_k(const float* __restrict__ x) {
    __shared__ float tile[32][33];
    int b = blockIdx.z / NT, t = blockIdx.z % NT;
    const float* xb = x + ((size_t)b * NT + t) * SP;
    float* og = g_xg + ((size_t)b * NT + t) * SP;
    int Y0 = blockIdx.y * 32, X0 = blockIdx.x * 32;
#pragma unroll
    for (int k = 0; k < 4; k++) {
        int row = threadIdx.y + k * 8;
        tile[row][threadIdx.x] = xb[(size_t)(Y0 + row) * NYX + X0 + threadIdx.x];
    }
    __syncthreads();
#pragma unroll
    for (int k = 0; k < 4; k++) {
        int row = threadIdx.y + k * 8;
        og[(size_t)(X0 + row) * NYX + Y0 + threadIdx.x] = tile[threadIdx.x][row];
    }
}

// ---------------------------------------------------------------------------
// M(u) core. QX=false: write result plane. QX=true (v-pass): don't store v;
// accumulate xout partials: contrib = xg*(v + 1_{1<=t<=7}*xg - w[t-1] - w[t+1]).
// ---------------------------------------------------------------------------
template <bool QX>
__global__ void applyM_k(const float* __restrict__ u, float* __restrict__ og) {
    __shared__ float tile[10][36];
    __shared__ float red[256];
    int bt = blockIdx.z;
    int b = bt / NT, t = bt % NT;
    int A0 = blockIdx.y * 8, C0 = blockIdx.x * 32;
    const float* ub = u + (size_t)bt * SP;
    int tid = threadIdx.y * 32 + threadIdx.x;
    for (int i = tid; i < 10 * 34; i += 256) {
        int rr = i / 34, cc = i % 34;
        int A = A0 - 1 + rr, C = C0 - 1 + cc;
        tile[rr][cc] = (A >= 0 && A < NYX && C >= 0 && C < NYX)
                       ? ub[(size_t)A * NYX + C] : 0.0f;
    }
    __syncthreads();
    int a = threadIdx.y, c = threadIdx.x;
    float u0 = tile[a + 1][c + 1];
    float xp = tile[a + 2][c + 1], xm = tile[a][c + 1];
    float yp = tile[a + 1][c + 2], ym = tile[a + 1][c];
    float pp = tile[a + 2][c + 2], pm = tile[a + 2][c];
    float mp = tile[a][c + 2],     mm = tile[a][c];
    float dx  = 0.5f * (xp - xm);
    float dy  = 0.5f * (yp - ym);
    float dxx = xp - 2.0f * u0 + xm;
    float dyy = yp - 2.0f * u0 + ym;
    float dxy = 0.25f * (pp - pm - mp + mm);

    int s = (A0 + a) * NYX + (C0 + c);
    size_t pl = (size_t)bt * SP + s;
    const float* pb = g_p3 + (size_t)b * C3 * SP + s;
    float gm = sp10(pb[(size_t)(27 + t) * SP]);
    float vx = pb[(size_t)(36 + t) * SP];
    float vy = pb[(size_t)(45 + t) * SP];
    float kap = g_kg[pl];
    float m1  = g_m1[pl];
    float m2  = g_m2[pl];

    float r = u0 + kap * kap * u0 + m1 * dx + m2 * dy
            - ((gm + vx * vx) * dxx + 2.0f * vx * vy * dxy + (gm + vy * vy) * dyy);

    if (!QX) {
        og[pl] = r;
    } else {
        float xgv = g_xg[pl];
        float q = r;
        if (t >= 1) { q -= u[pl - SP]; }
        if (t <= 7) { q -= u[pl + SP]; }
        if (t >= 1 && t <= 7) q += xgv;
        red[tid] = xgv * q;
        __syncthreads();
        for (int st = 128; st > 0; st >>= 1) {
            if (tid < st) red[tid] += red[tid + st];
            __syncthreads();
        }
        if (tid == 0) {
            int bi = t * 256 + blockIdx.y * 8 + blockIdx.x;
            g_part[b * NPART + bi] = red[0];
        }
    }
}

// ---------------------------------------------------------------------------
__global__ void final_reduce_k(float* __restrict__ out) {
    __shared__ float red[256];
    int b = blockIdx.x;
    float s = 0.0f;
    for (int i = threadIdx.x; i < NPART; i += 256) s += g_part[b * NPART + i];
    red[threadIdx.x] = s;
    __syncthreads();
    for (int st = 128; st > 0; st >>= 1) {
        if (threadIdx.x < st) red[threadIdx.x] += red[threadIdx.x + st];
        __syncthreads();
    }
    if (threadIdx.x == 0) out[OFF_XOUT + b] = red[0];
}

// ---------------------------------------------------------------------------
extern "C" void kernel_launch(void* const* d_in, const int* in_sizes, int n_in,
                              void* d_out, int out_size) {
    const float* x  = (const float*)d_in[0];
    const float* w1 = (const float*)d_in[4];
    const float* w2 = (const float*)d_in[5];
    const float* w3 = (const float*)d_in[6];
    float* out = (float*)d_out;

    float *p1, *p2, *p3, *xg, *wg;
    cudaGetSymbolAddress((void**)&p1, g_p1);
    cudaGetSymbolAddress((void**)&p2, g_p2);
    cudaGetSymbolAddress((void**)&p3, g_p3);
    cudaGetSymbolAddress((void**)&xg, g_xg);
    cudaGetSymbolAddress((void**)&wg, g_w);

    static cudaStream_t s1 = nullptr;
    static cudaEvent_t ev0 = nullptr, evT = nullptr, evC = nullptr, ev1 = nullptr;
    if (!s1) {
        cudaStreamCreateWithFlags(&s1, cudaStreamNonBlocking);
        cudaEventCreateWithFlags(&ev0, cudaEventDisableTiming);
        cudaEventCreateWithFlags(&evT, cudaEventDisableTiming);
        cudaEventCreateWithFlags(&evC, cudaEventDisableTiming);
        cudaEventCreateWithFlags(&ev1, cudaEventDisableTiming);
    }

    const int smem1 = (9  * 3 + 1) * TSK * 4 + 6  * 16 * 4;
    const int smem2 = (10 * 3 + 1) * TSK * 4 + 6  * 16 * 4;
    const int smem3 = (20 * 3 + 1) * TSK * 4 + 12 * 16 * 4;
    cudaFuncSetAttribute((const void*)conv_mma_f16_k<9,  true,  1, 6,  C1, 0,  4>, cudaFuncAttributeMaxDynamicSharedMemorySize, smem1);
    cudaFuncSetAttribute((const void*)conv_mma_f16_k<10, true,  2, 6,  C2, 6,  3>, cudaFuncAttributeMaxDynamicSharedMemorySize, smem2);
    cudaFuncSetAttribute((const void*)conv_mma_bf16_k<20, false, 4, 12, C3, 18, 2>, cudaFuncAttributeMaxDynamicSharedMemorySize, smem3);

    // fork: transpose on side stream
    cudaEventRecord(ev0, 0);
    cudaStreamWaitEvent(s1, ev0, 0);
    transpose_k<<<dim3(8, 8, NB * NT), dim3(32, 8), 0, s1>>>(x);
    cudaEventRecord(evT, s1);

    // main: conv chain
    prep_w_k<<<9, 256>>>(w1, w2, w3);
    conv_mma_f16_k<9,  true,  1, 6,  C1, 0,  4><<<dim3(1, 256, NB), dim3(32, 8), smem1>>>(x,  p1);
    conv_mma_f16_k<10, true,  2, 6,  C2, 6,  3><<<dim3(1, 256, NB), dim3(32, 8), smem2>>>(p1, p2);
    conv_mma_bf16_k<20, false, 4, 12, C3, 18, 2><<<dim3(1, 256, NB), dim3(32, 8), smem3>>>(p2, p3);
    cudaEventRecord(evC, 0);

    // side: epiH
    cudaStreamWaitEvent(s1, evC, 0);
    epiH_k<<<(NB * SP) / 256, 256, 0, s1>>>(out);
    cudaEventRecord(ev1, s1);

    // main: epiA -> PDE pipeline (v-pass fused with qx)
    epiA_scramble_k<<<dim3(256, NB), 256>>>(out);
    cudaStreamWaitEvent(0, evT, 0);
    applyM_k<false><<<dim3(8, 32, NB * NT), dim3(32, 8)>>>(xg, wg);
    applyM_k<true ><<<dim3(8, 32, NB * NT), dim3(32, 8)>>>(wg, nullptr);
    cudaStreamWaitEvent(0, ev1, 0);
    final_reduce_k<<<NB, 256>>>(out);
}

// round 15
// speedup vs baseline: 1.1247x; 1.0279x over previous
#include <cuda_runtime.h>
#include <cuda_bf16.h>
#include <cstdint>

#define NB 16
#define NT 9
#define NYX 256
#define SP 65536
#define C1 10
#define C2 20
#define C3 54

#define OFF_XOUT 0
#define OFF_KAP  16
#define OFF_M    9437200
#define OFF_H    28311568

#define TSK 288
#define NPART 2304

__device__ float    g_p1[NB * C1 * SP];
__device__ uint32_t g_p2[NB * C2 * SP];   // packed bf16 hi|lo
__device__ float    g_p3[NB * C3 * SP];
__device__ float g_xg[NB * NT * SP];
__device__ float g_w [NB * NT * SP];
__device__ float g_kg [NB * NT * SP];
__device__ float g_m1 [NB * NT * SP];
__device__ float g_m2 [NB * NT * SP];
__device__ float g_part[NB * NPART];
// A-fragments: conv1 slots 0..5 (MT1,KS6, fp16); conv2 6..17 (MT2,KS6, fp16);
// conv3 18..65 (MT4,KS12, bf16).
__device__ uint4 g_wfrag[66 * 32 * 2];

__device__ __forceinline__ float sp10(float x) {
    float z = 10.0f * x;
    return (fmaxf(z, 0.0f) + log1pf(expf(-fabsf(z)))) * 0.1f;
}
__device__ __forceinline__ uint32_t bfpack(float lo, float hi) {
    uint32_t r; asm("cvt.rn.bf16x2.f32 %0, %1, %2;" : "=r"(r) : "f"(hi), "f"(lo));
    return r;
}
__device__ __forceinline__ uint32_t hfpack(float lo, float hi) {
    uint32_t r; asm("cvt.rn.f16x2.f32 %0, %1, %2;" : "=r"(r) : "f"(hi), "f"(lo));
    return r;
}
__device__ __forceinline__ float bf_lo(uint32_t h) { return __uint_as_float(h << 16); }
__device__ __forceinline__ float bf_hi(uint32_t h) { return __uint_as_float(h & 0xFFFF0000u); }
// split x into packed u32: [31:16]=bf16_rn(x), [15:0]=bf16_rn(x - hi)
__device__ __forceinline__ uint32_t packsplit(float x) {
    uint32_t h = bfpack(x, x);
    float hf = bf_hi(h);
    uint32_t l = bfpack(x - hf, x - hf);
    return (h & 0xFFFF0000u) | (l >> 16);
}

__device__ __forceinline__ void mma_bf16(float* d, const uint32_t* a, const uint32_t* b) {
    asm("mma.sync.aligned.m16n8k16.row.col.f32.bf16.bf16.f32 "
        "{%0,%1,%2,%3}, {%4,%5,%6,%7}, {%8,%9}, {%0,%1,%2,%3};"
        : "+f"(d[0]), "+f"(d[1]), "+f"(d[2]), "+f"(d[3])
        : "r"(a[0]), "r"(a[1]), "r"(a[2]), "r"(a[3]), "r"(b[0]), "r"(b[1]));
}
__device__ __forceinline__ void mma_f16(float* d, const uint32_t* a, const uint32_t* b) {
    asm("mma.sync.aligned.m16n8k16.row.col.f32.f16.f16.f32 "
        "{%0,%1,%2,%3}, {%4,%5,%6,%7}, {%8,%9}, {%0,%1,%2,%3};"
        : "+f"(d[0]), "+f"(d[1]), "+f"(d[2]), "+f"(d[3])
        : "r"(a[0]), "r"(a[1]), "r"(a[2]), "r"(a[3]), "r"(b[0]), "r"(b[1]));
}

// ---------------------------------------------------------------------------
__global__ void prep_w_k(const float* __restrict__ w1,
                         const float* __restrict__ w2,
                         const float* __restrict__ w3) {
    int idx = blockIdx.x * blockDim.x + threadIdx.x;
    if (idx >= 66 * 32) return;
    int lane = idx & 31;
    int slot = idx >> 5;
    const float* w; int K, COUT, mt, ks; bool f16;
    if (slot < 6)       { w = w1; K = 81;  COUT = C1; mt = 0;               ks = slot;  f16 = true; }
    else if (slot < 18) { w = w2; K = 90;  COUT = C2; int s = slot - 6;  mt = s / 6;  ks = s % 6;  f16 = true; }
    else                { w = w3; K = 180; COUT = C3; int s = slot - 18; mt = s / 12; ks = s % 12; f16 = false; }
    int g = lane >> 2, tig = lane & 3;
    uint32_t hi[4], lo[4];
#pragma unroll
    for (int i = 0; i < 4; i++) {
        int row = mt * 16 + g + (i & 1) * 8;
        int k   = ks * 16 + (i >> 1) * 8 + 2 * tig;
        float w0 = (row < COUT && k     < K) ? w[row * K + k]     : 0.0f;
        float w1v = (row < COUT && k + 1 < K) ? w[row * K + k + 1] : 0.0f;
        if (f16) {
            float h0 = __half2float(__float2half_rn(w0));
            float h1 = __half2float(__float2half_rn(w1v));
            hi[i] = hfpack(h0, h1);
            lo[i] = hfpack(w0 - h0, w1v - h1);
        } else {
            uint32_t h = bfpack(w0, w1v);
            hi[i] = h;
            lo[i] = bfpack(w0 - bf_lo(h), w1v - bf_hi(h));
        }
    }
    int base = (slot * 32 + lane) * 2;
    g_wfrag[base]     = make_uint4(hi[0], hi[1], hi[2], hi[3]);
    g_wfrag[base + 1] = make_uint4(lo[0], lo[1], lo[2], lo[3]);
}

// ---------------------------------------------------------------------------
// conv1/conv2: fp16 2-pass, TWO output rows per block. grid (1, 128, NB).
// Tile: 4 src rows (y0-1..y0+2), skew 8*(rr%3). koff: [2][KS*16].
// PACK_OUT: epilogue writes packed bf16 hi|lo u32 (for conv3 consumption).
// ---------------------------------------------------------------------------
template <int CIN, bool RELU_IN, int MT, int KS, int COUT, int WOFF, int MAXB, bool PACK_OUT>
__global__ void __launch_bounds__(256, MAXB)
conv_f16_2r_k(const float* __restrict__ in, void* __restrict__ outv) {
    extern __shared__ float sh[];
    const int ZR = CIN * 4;
    float* tile = sh;
    int* koff = (int*)(sh + (ZR + 1) * TSK);

    const int b  = blockIdx.z;
    const int y0 = blockIdx.y * 2;
    const int tid = threadIdx.y * 32 + threadIdx.x;

    const float* inb = in + (size_t)b * CIN * SP;
    for (int idx = tid; idx < CIN * 4 * 258; idx += 256) {
        int c  = idx % 258;
        int rr = (idx / 258) & 3;
        int ci = idx / (258 * 4);
        int gy = y0 - 1 + rr;
        int gx = c - 1;
        float v = 0.0f;
        if (gy >= 0 && gy < NYX && gx >= 0 && gx < NYX) {
            v = inb[ci * SP + gy * NYX + gx];
            if (RELU_IN) v = fmaxf(v, 0.0f);
        }
        tile[(ci * 4 + rr) * TSK + 8 * (rr % 3) + c] = v;
    }
    for (int i = tid; i < TSK; i += 256) tile[ZR * TSK + i] = 0.0f;
    for (int k = tid; k < 2 * KS * 16; k += 256) {
        int r  = k / (KS * 16);
        int kk = k % (KS * 16);
        int off;
        if (kk < CIN * 9) {
            int ci = kk / 9, tap = kk % 9;
            int ky = tap / 3;
            int rr = ky + r;
            off = (ci * 4 + rr) * TSK + 8 * (rr % 3) + tap % 3;
        } else off = ZR * TSK;
        koff[k] = off;
    }
    __syncthreads();

    const int warp = threadIdx.y;
    const int lane = threadIdx.x;
    const int g = lane >> 2, tig = lane & 3;
    const int nbase = warp * 32;

    float acc[2][MT][4][4];
#pragma unroll
    for (int r = 0; r < 2; r++)
#pragma unroll
        for (int m = 0; m < MT; m++)
#pragma unroll
            for (int n = 0; n < 4; n++)
#pragma unroll
                for (int q = 0; q < 4; q++) acc[r][m][n][q] = 0.0f;

    for (int ks = 0; ks < KS; ks++) {
        uint32_t bfr[2][4][2];
#pragma unroll
        for (int r = 0; r < 2; r++) {
            const int* kf = koff + r * KS * 16 + ks * 16;
            int o00 = kf[2 * tig], o01 = kf[2 * tig + 1];
            int o10 = kf[8 + 2 * tig], o11 = kf[8 + 2 * tig + 1];
#pragma unroll
            for (int nt = 0; nt < 4; nt++) {
                int n = nbase + nt * 8 + g;
                bfr[r][nt][0] = hfpack(tile[o00 + n], tile[o01 + n]);
                bfr[r][nt][1] = hfpack(tile[o10 + n], tile[o11 + n]);
            }
        }
#pragma unroll
        for (int mt = 0; mt < MT; mt++) {
            int base = ((WOFF + mt * KS + ks) * 32 + lane) * 2;
            uint4 ah = g_wfrag[base];
            uint4 al = g_wfrag[base + 1];
            uint32_t ahi[4] = { ah.x, ah.y, ah.z, ah.w };
            uint32_t alo[4] = { al.x, al.y, al.z, al.w };
#pragma unroll
            for (int r = 0; r < 2; r++)
#pragma unroll
                for (int nt = 0; nt < 4; nt++) {
                    mma_f16(acc[r][mt][nt], ahi, bfr[r][nt]);
                    mma_f16(acc[r][mt][nt], alo, bfr[r][nt]);
                }
        }
    }

#pragma unroll
    for (int r = 0; r < 2; r++) {
        int gy = y0 + r;
#pragma unroll
        for (int mt = 0; mt < MT; mt++) {
            int co0 = mt * 16 + g;
#pragma unroll
            for (int nt = 0; nt < 4; nt++) {
                int px = nbase + nt * 8 + 2 * tig;
                size_t o0 = ((size_t)b * COUT + co0) * SP + (size_t)gy * NYX + px;
                if (PACK_OUT) {
                    uint32_t* op = (uint32_t*)outv;
                    if (co0 < COUT)
                        *reinterpret_cast<uint2*>(op + o0) =
                            make_uint2(packsplit(acc[r][mt][nt][0]), packsplit(acc[r][mt][nt][1]));
                    if (co0 + 8 < COUT)
                        *reinterpret_cast<uint2*>(op + o0 + (size_t)8 * SP) =
                            make_uint2(packsplit(acc[r][mt][nt][2]), packsplit(acc[r][mt][nt][3]));
                } else {
                    float* op = (float*)outv;
                    if (co0 < COUT)
                        *reinterpret_cast<float2*>(op + o0) =
                            make_float2(acc[r][mt][nt][0], acc[r][mt][nt][1]);
                    if (co0 + 8 < COUT)
                        *reinterpret_cast<float2*>(op + o0 + (size_t)8 * SP) =
                            make_float2(acc[r][mt][nt][2], acc[r][mt][nt][3]);
                }
            }
        }
    }
}

// ---------------------------------------------------------------------------
// conv3: bf16 3-pass, input pre-split packed (hi|lo u32). B-build = LDS + PRMT.
// ---------------------------------------------------------------------------
template <int CIN, int MT, int KS, int COUT, int WOFF, int MAXB>
__global__ void __launch_bounds__(256, MAXB)
conv_bf16_packed_k(const uint32_t* __restrict__ in, float* __restrict__ out) {
    extern __shared__ float sh[];
    const int ZR = CIN * 3;
    uint32_t* tile = (uint32_t*)sh;
    int* koff = (int*)(sh + (ZR + 1) * TSK);

    const int b  = blockIdx.z;
    const int y0 = blockIdx.y;
    const int tid = threadIdx.y * 32 + threadIdx.x;

    const uint32_t* inb = in + (size_t)b * CIN * SP;
    for (int idx = tid; idx < CIN * 3 * 258; idx += 256) {
        int c  = idx % 258;
        int rr = (idx / 258) % 3;
        int ci = idx / 774;
        int gy = y0 - 1 + rr;
        int gx = c - 1;
        uint32_t v = 0u;
        if (gy >= 0 && gy < NYX && gx >= 0 && gx < NYX)
            v = inb[ci * SP + gy * NYX + gx];
        tile[(ci * 3 + rr) * TSK + 8 * rr + c] = v;
    }
    for (int i = tid; i < TSK; i += 256) tile[ZR * TSK + i] = 0u;
    for (int k = tid; k < KS * 16; k += 256) {
        if (k < CIN * 9) {
            int ci = k / 9, r = k % 9;
            int ky = r / 3;
            koff[k] = (ci * 3 + ky) * TSK + 8 * ky + (r % 3);
        } else {
            koff[k] = ZR * TSK;
        }
    }
    __syncthreads();

    const int warp = threadIdx.y;
    const int lane = threadIdx.x;
    const int g = lane >> 2, tig = lane & 3;
    const int nbase = warp * 32;

    float acc[MT][4][4];
#pragma unroll
    for (int m = 0; m < MT; m++)
#pragma unroll
        for (int n = 0; n < 4; n++)
#pragma unroll
            for (int q = 0; q < 4; q++) acc[m][n][q] = 0.0f;

    for (int ks = 0; ks < KS; ks++) {
        int o00 = koff[ks * 16 + 2 * tig];
        int o01 = koff[ks * 16 + 2 * tig + 1];
        int o10 = koff[ks * 16 + 8 + 2 * tig];
        int o11 = koff[ks * 16 + 8 + 2 * tig + 1];
        uint32_t bhi[4][2], blo[4][2];
#pragma unroll
        for (int nt = 0; nt < 4; nt++) {
            int n = nbase + nt * 8 + g;
            uint32_t w00 = tile[o00 + n], w01 = tile[o01 + n];
            uint32_t w10 = tile[o10 + n], w11 = tile[o11 + n];
            bhi[nt][0] = __byte_perm(w00, w01, 0x7632);
            blo[nt][0] = __byte_perm(w00, w01, 0x5410);
            bhi[nt][1] = __byte_perm(w10, w11, 0x7632);
            blo[nt][1] = __byte_perm(w10, w11, 0x5410);
        }
#pragma unroll
        for (int mt = 0; mt < MT; mt++) {
            int base = ((WOFF + mt * KS + ks) * 32 + lane) * 2;
            uint4 ah = g_wfrag[base];
            uint4 al = g_wfrag[base + 1];
            uint32_t ahi[4] = { ah.x, ah.y, ah.z, ah.w };
            uint32_t alo[4] = { al.x, al.y, al.z, al.w };
#pragma unroll
            for (int nt = 0; nt < 4; nt++) {
                mma_bf16(acc[mt][nt], ahi, bhi[nt]);
                mma_bf16(acc[mt][nt], ahi, blo[nt]);
                mma_bf16(acc[mt][nt], alo, bhi[nt]);
            }
        }
    }

#pragma unroll
    for (int mt = 0; mt < MT; mt++) {
        int co0 = mt * 16 + g;
#pragma unroll
        for (int nt = 0; nt < 4; nt++) {
            int px = nbase + nt * 8 + 2 * tig;
            float* op = out + ((size_t)b * COUT + co0) * SP + (size_t)y0 * NYX + px;
            if (co0 < COUT)
                *reinterpret_cast<float2*>(op) = make_float2(acc[mt][nt][0], acc[mt][nt][1]);
            if (co0 + 8 < COUT)
                *reinterpret_cast<float2*>(op + (size_t)8 * SP) = make_float2(acc[mt][nt][2], acc[mt][nt][3]);
        }
    }
}

// ---------------------------------------------------------------------------
__global__ void epiA_scramble_k(float* __restrict__ out) {
    __shared__ float shk[2304], shm1[2304], shm2[2304];
    int b = blockIdx.y;
    int chunk = blockIdx.x;
    int L0 = chunk * 2304;
    int s0 = chunk * 256;
    const float* src = g_p3 + (size_t)b * C3 * SP;
    float* okap = out + OFF_KAP + (size_t)b * 9 * SP;
    float* om   = out + OFF_M   + (size_t)b * 18 * SP;
#pragma unroll
    for (int it = 0; it < 9; ++it) {
        int i = it * 256 + threadIdx.x;
        int L = L0 + i;
        float k  = sp10(src[L]);
        float m1 = src[9 * SP + L];
        float m2 = src[18 * SP + L];
        shk[i] = k; shm1[i] = m1; shm2[i] = m2;
        okap[L] = k;
        om[L] = m1;
        om[9 * SP + L] = m2;
    }
    __syncthreads();
#pragma unroll
    for (int it = 0; it < 9; ++it) {
        int i = it * 256 + threadIdx.x;
        int so = i & 255;
        int t = i >> 8;
        int si = 9 * so + t;
        size_t dst = ((size_t)b * 9 + t) * SP + s0 + so;
        g_kg[dst] = shk[si];
        g_m1[dst] = shm1[si];
        g_m2[dst] = shm2[si];
    }
}

// ---------------------------------------------------------------------------
__global__ void epiH_k(float* __restrict__ out) {
    int gid = blockIdx.x * blockDim.x + threadIdx.x;
    int b = gid >> 16;
    int s = gid & (SP - 1);
    const float* pb = g_p3 + (size_t)b * C3 * SP + s;
    float gm[NT], vx[NT], vy[NT];
#pragma unroll
    for (int t = 0; t < NT; t++) {
        gm[t] = sp10(pb[(size_t)(27 + t) * SP]);
        vx[t] = pb[(size_t)(36 + t) * SP];
        vy[t] = pb[(size_t)(45 + t) * SP];
    }
    const size_t PLANE = (size_t)SP * NT;
    size_t base = OFF_H + (size_t)b * 4 * PLANE + (size_t)s * NT;
#pragma unroll
    for (int t = 0; t < NT; t++) out[base + t] = gm[t] + vx[t] * vx[t];
#pragma unroll
    for (int t = 0; t < NT; t++) {
        float xy = vx[t] * vy[t];
        out[base + PLANE + t]     = xy;
        out[base + 2 * PLANE + t] = xy;
    }
#pragma unroll
    for (int t = 0; t < NT; t++) out[base + 3 * PLANE + t] = gm[t] + vy[t] * vy[t];
}

// ---------------------------------------------------------------------------
__global__ void transpose_k(const float* __restrict__ x) {
    __shared__ float tile[32][33];
    int b = blockIdx.z / NT, t = blockIdx.z % NT;
    const float* xb = x + ((size_t)b * NT + t) * SP;
    float* og = g_xg + ((size_t)b * NT + t) * SP;
    int Y0 = blockIdx.y * 32, X0 = blockIdx.x * 32;
#pragma unroll
    for (int k = 0; k < 4; k++) {
        int row = threadIdx.y + k * 8;
        tile[row][threadIdx.x] = xb[(size_t)(Y0 + row) * NYX + X0 + threadIdx.x];
    }
    __syncthreads();
#pragma unroll
    for (int k = 0; k < 4; k++) {
        int row = threadIdx.y + k * 8;
        og[(size_t)(X0 + row) * NYX + Y0 + threadIdx.x] = tile[threadIdx.x][row];
    }
}

// ---------------------------------------------------------------------------
template <bool QX>
__global__ void applyM_k(const float* __restrict__ u, float* __restrict__ og) {
    __shared__ float tile[10][36];
    __shared__ float red[256];
    int bt = blockIdx.z;
    int b = bt / NT, t = bt % NT;
    int A0 = blockIdx.y * 8, C0 = blockIdx.x * 32;
    const float* ub = u + (size_t)bt * SP;
    int tid = threadIdx.y * 32 + threadIdx.x;
    for (int i = tid; i < 10 * 34; i += 256) {
        int rr = i / 34, cc = i % 34;
        int A = A0 - 1 + rr, C = C0 - 1 + cc;
        tile[rr][cc] = (A >= 0 && A < NYX && C >= 0 && C < NYX)
                       ? ub[(size_t)A * NYX + C] : 0.0f;
    }
    __syncthreads();
    int a = threadIdx.y, c = threadIdx.x;
    float u0 = tile[a + 1][c + 1];
    float xp = tile[a + 2][c + 1], xm = tile[a][c + 1];
    float yp = tile[a + 1][c + 2], ym = tile[a + 1][c];
    float pp = tile[a + 2][c + 2], pm = tile[a + 2][c];
    float mp = tile[a][c + 2],     mm = tile[a][c];
    float dx  = 0.5f * (xp - xm);
    float dy  = 0.5f * (yp - ym);
    float dxx = xp - 2.0f * u0 + xm;
    float dyy = yp - 2.0f * u0 + ym;
    float dxy = 0.25f * (pp - pm - mp + mm);

    int s = (A0 + a) * NYX + (C0 + c);
    size_t pl = (size_t)bt * SP + s;
    const float* pb = g_p3 + (size_t)b * C3 * SP + s;
    float gm = sp10(pb[(size_t)(27 + t) * SP]);
    float vx = pb[(size_t)(36 + t) * SP];
    float vy = pb[(size_t)(45 + t) * SP];
    float kap = g_kg[pl];
    float m1  = g_m1[pl];
    float m2  = g_m2[pl];

    float r = u0 + kap * kap * u0 + m1 * dx + m2 * dy
            - ((gm + vx * vx) * dxx + 2.0f * vx * vy * dxy + (gm + vy * vy) * dyy);

    if (!QX) {
        og[pl] = r;
    } else {
        float xgv = g_xg[pl];
        float q = r;
        if (t >= 1) { q -= u[pl - SP]; }
        if (t <= 7) { q -= u[pl + SP]; }
        if (t >= 1 && t <= 7) q += xgv;
        red[tid] = xgv * q;
        __syncthreads();
        for (int st = 128; st > 0; st >>= 1) {
            if (tid < st) red[tid] += red[tid + st];
            __syncthreads();
        }
        if (tid == 0) {
            int bi = t * 256 + blockIdx.y * 8 + blockIdx.x;
            g_part[b * NPART + bi] = red[0];
        }
    }
}

// ---------------------------------------------------------------------------
__global__ void final_reduce_k(float* __restrict__ out) {
    __shared__ float red[256];
    int b = blockIdx.x;
    float s = 0.0f;
    for (int i = threadIdx.x; i < NPART; i += 256) s += g_part[b * NPART + i];
    red[threadIdx.x] = s;
    __syncthreads();
    for (int st = 128; st > 0; st >>= 1) {
        if (threadIdx.x < st) red[threadIdx.x] += red[threadIdx.x + st];
        __syncthreads();
    }
    if (threadIdx.x == 0) out[OFF_XOUT + b] = red[0];
}

// ---------------------------------------------------------------------------
extern "C" void kernel_launch(void* const* d_in, const int* in_sizes, int n_in,
                              void* d_out, int out_size) {
    const float* x  = (const float*)d_in[0];
    const float* w1 = (const float*)d_in[4];
    const float* w2 = (const float*)d_in[5];
    const float* w3 = (const float*)d_in[6];
    float* out = (float*)d_out;

    float *p1, *p3, *xg, *wg;
    uint32_t* p2;
    cudaGetSymbolAddress((void**)&p1, g_p1);
    cudaGetSymbolAddress((void**)&p2, g_p2);
    cudaGetSymbolAddress((void**)&p3, g_p3);
    cudaGetSymbolAddress((void**)&xg, g_xg);
    cudaGetSymbolAddress((void**)&wg, g_w);

    static cudaStream_t s1 = nullptr;
    static cudaEvent_t ev0 = nullptr, evT = nullptr, evC = nullptr, ev1 = nullptr;
    if (!s1) {
        cudaStreamCreateWithFlags(&s1, cudaStreamNonBlocking);
        cudaEventCreateWithFlags(&ev0, cudaEventDisableTiming);
        cudaEventCreateWithFlags(&evT, cudaEventDisableTiming);
        cudaEventCreateWithFlags(&evC, cudaEventDisableTiming);
        cudaEventCreateWithFlags(&ev1, cudaEventDisableTiming);
    }

    const int smem1 = (9  * 4 + 1) * TSK * 4 + 2 * 6 * 16 * 4;   // 43,392
    const int smem2 = (10 * 4 + 1) * TSK * 4 + 2 * 6 * 16 * 4;   // 48,000
    const int smem3 = (20 * 3 + 1) * TSK * 4 + 12 * 16 * 4;      // 71,040
    cudaFuncSetAttribute((const void*)conv_f16_2r_k<9,  true, 1, 6, C1, 0, 3, false>, cudaFuncAttributeMaxDynamicSharedMemorySize, smem1);
    cudaFuncSetAttribute((const void*)conv_f16_2r_k<10, true, 2, 6, C2, 6, 2, true >, cudaFuncAttributeMaxDynamicSharedMemorySize, smem2);
    cudaFuncSetAttribute((const void*)conv_bf16_packed_k<20, 4, 12, C3, 18, 2>, cudaFuncAttributeMaxDynamicSharedMemorySize, smem3);

    // fork: transpose on side stream
    cudaEventRecord(ev0, 0);
    cudaStreamWaitEvent(s1, ev0, 0);
    transpose_k<<<dim3(8, 8, NB * NT), dim3(32, 8), 0, s1>>>(x);
    cudaEventRecord(evT, s1);

    // main: conv chain
    prep_w_k<<<9, 256>>>(w1, w2, w3);
    conv_f16_2r_k<9,  true, 1, 6, C1, 0, 3, false><<<dim3(1, 128, NB), dim3(32, 8), smem1>>>(x,  p1);
    conv_f16_2r_k<10, true, 2, 6, C2, 6, 2, true ><<<dim3(1, 128, NB), dim3(32, 8), smem2>>>(p1, p2);
    conv_bf16_packed_k<20, 4, 12, C3, 18, 2><<<dim3(1, 256, NB), dim3(32, 8), smem3>>>(p2, p3);
    cudaEventRecord(evC, 0);

    // side: epiH
    cudaStreamWaitEvent(s1, evC, 0);
    epiH_k<<<(NB * SP) / 256, 256, 0, s1>>>(out);
    cudaEventRecord(ev1, s1);

    // main: epiA -> PDE pipeline (v-pass fused with qx)
    epiA_scramble_k<<<dim3(256, NB), 256>>>(out);
    cudaStreamWaitEvent(0, evT, 0);
    applyM_k<false><<<dim3(8, 32, NB * NT), dim3(32, 8)>>>(xg, wg);
    applyM_k<true ><<<dim3(8, 32, NB * NT), dim3(32, 8)>>>(wg, nullptr);
    cudaStreamWaitEvent(0, ev1, 0);
    final_reduce_k<<<NB, 256>>>(out);
}

// round 16
// speedup vs baseline: 1.1302x; 1.0049x over previous
#include <cuda_runtime.h>
#include <cuda_bf16.h>
#include <cstdint>

#define NB 16
#define NT 9
#define NYX 256
#define SP 65536
#define C1 10
#define C2 20
#define C3 54

#define OFF_XOUT 0
#define OFF_KAP  16
#define OFF_M    9437200
#define OFF_H    28311568

#define TSK 288
#define NPART 2304

__device__ float    g_p1[NB * C1 * SP];
__device__ uint32_t g_p2[NB * C2 * SP];   // duplicated fp16x2
__device__ float    g_p3[NB * C3 * SP];
__device__ float g_xg[NB * NT * SP];
__device__ float g_w [NB * NT * SP];
__device__ float g_kg [NB * NT * SP];
__device__ float g_m1 [NB * NT * SP];
__device__ float g_m2 [NB * NT * SP];
__device__ float g_part[NB * NPART];
// fp16 A-fragments (hi,lo): conv1 slots 0..5 (MT1,KS6); conv2 6..17 (MT2,KS6);
// conv3 18..65 (MT4,KS12).
__device__ uint4 g_wfrag[66 * 32 * 2];

__device__ __forceinline__ float sp10(float x) {
    float z = 10.0f * x;
    return (fmaxf(z, 0.0f) + log1pf(expf(-fabsf(z)))) * 0.1f;
}
__device__ __forceinline__ uint32_t hfpack(float lo, float hi) {
    uint32_t r; asm("cvt.rn.f16x2.f32 %0, %1, %2;" : "=r"(r) : "f"(hi), "f"(lo));
    return r;
}
__device__ __forceinline__ void mma_f16(float* d, const uint32_t* a, const uint32_t* b) {
    asm("mma.sync.aligned.m16n8k16.row.col.f32.f16.f16.f32 "
        "{%0,%1,%2,%3}, {%4,%5,%6,%7}, {%8,%9}, {%0,%1,%2,%3};"
        : "+f"(d[0]), "+f"(d[1]), "+f"(d[2]), "+f"(d[3])
        : "r"(a[0]), "r"(a[1]), "r"(a[2]), "r"(a[3]), "r"(b[0]), "r"(b[1]));
}

// ---------------------------------------------------------------------------
// Prep: all conv weights -> fp16 hi/lo m16n8k16 A-fragments.
// ---------------------------------------------------------------------------
__global__ void prep_w_k(const float* __restrict__ w1,
                         const float* __restrict__ w2,
                         const float* __restrict__ w3) {
    int idx = blockIdx.x * blockDim.x + threadIdx.x;
    if (idx >= 66 * 32) return;
    int lane = idx & 31;
    int slot = idx >> 5;
    const float* w; int K, COUT, mt, ks;
    if (slot < 6)       { w = w1; K = 81;  COUT = C1; mt = 0;               ks = slot; }
    else if (slot < 18) { w = w2; K = 90;  COUT = C2; int s = slot - 6;  mt = s / 6;  ks = s % 6; }
    else                { w = w3; K = 180; COUT = C3; int s = slot - 18; mt = s / 12; ks = s % 12; }
    int g = lane >> 2, tig = lane & 3;
    uint32_t hi[4], lo[4];
#pragma unroll
    for (int i = 0; i < 4; i++) {
        int row = mt * 16 + g + (i & 1) * 8;
        int k   = ks * 16 + (i >> 1) * 8 + 2 * tig;
        float w0 = (row < COUT && k     < K) ? w[row * K + k]     : 0.0f;
        float w1v = (row < COUT && k + 1 < K) ? w[row * K + k + 1] : 0.0f;
        float h0 = __half2float(__float2half_rn(w0));
        float h1 = __half2float(__float2half_rn(w1v));
        hi[i] = hfpack(h0, h1);
        lo[i] = hfpack(w0 - h0, w1v - h1);
    }
    int base = (slot * 32 + lane) * 2;
    g_wfrag[base]     = make_uint4(hi[0], hi[1], hi[2], hi[3]);
    g_wfrag[base + 1] = make_uint4(lo[0], lo[1], lo[2], lo[3]);
}

// ---------------------------------------------------------------------------
// conv1/conv2: fp16 2-pass, TWO output rows per block. grid (1, 128, NB).
// PACK_OUT: write duplicated fp16x2 (for conv3 consumption).
// ---------------------------------------------------------------------------
template <int CIN, bool RELU_IN, int MT, int KS, int COUT, int WOFF, int MAXB, bool PACK_OUT>
__global__ void __launch_bounds__(256, MAXB)
conv_f16_2r_k(const float* __restrict__ in, void* __restrict__ outv) {
    extern __shared__ float sh[];
    const int ZR = CIN * 4;
    float* tile = sh;
    int* koff = (int*)(sh + (ZR + 1) * TSK);

    const int b  = blockIdx.z;
    const int y0 = blockIdx.y * 2;
    const int tid = threadIdx.y * 32 + threadIdx.x;

    const float* inb = in + (size_t)b * CIN * SP;
    for (int idx = tid; idx < CIN * 4 * 258; idx += 256) {
        int c  = idx % 258;
        int rr = (idx / 258) & 3;
        int ci = idx / (258 * 4);
        int gy = y0 - 1 + rr;
        int gx = c - 1;
        float v = 0.0f;
        if (gy >= 0 && gy < NYX && gx >= 0 && gx < NYX) {
            v = inb[ci * SP + gy * NYX + gx];
            if (RELU_IN) v = fmaxf(v, 0.0f);
        }
        tile[(ci * 4 + rr) * TSK + 8 * (rr % 3) + c] = v;
    }
    for (int i = tid; i < TSK; i += 256) tile[ZR * TSK + i] = 0.0f;
    for (int k = tid; k < 2 * KS * 16; k += 256) {
        int r  = k / (KS * 16);
        int kk = k % (KS * 16);
        int off;
        if (kk < CIN * 9) {
            int ci = kk / 9, tap = kk % 9;
            int ky = tap / 3;
            int rr = ky + r;
            off = (ci * 4 + rr) * TSK + 8 * (rr % 3) + tap % 3;
        } else off = ZR * TSK;
        koff[k] = off;
    }
    __syncthreads();

    const int warp = threadIdx.y;
    const int lane = threadIdx.x;
    const int g = lane >> 2, tig = lane & 3;
    const int nbase = warp * 32;

    float acc[2][MT][4][4];
#pragma unroll
    for (int r = 0; r < 2; r++)
#pragma unroll
        for (int m = 0; m < MT; m++)
#pragma unroll
            for (int n = 0; n < 4; n++)
#pragma unroll
                for (int q = 0; q < 4; q++) acc[r][m][n][q] = 0.0f;

    for (int ks = 0; ks < KS; ks++) {
        uint32_t bfr[2][4][2];
#pragma unroll
        for (int r = 0; r < 2; r++) {
            const int* kf = koff + r * KS * 16 + ks * 16;
            int o00 = kf[2 * tig], o01 = kf[2 * tig + 1];
            int o10 = kf[8 + 2 * tig], o11 = kf[8 + 2 * tig + 1];
#pragma unroll
            for (int nt = 0; nt < 4; nt++) {
                int n = nbase + nt * 8 + g;
                bfr[r][nt][0] = hfpack(tile[o00 + n], tile[o01 + n]);
                bfr[r][nt][1] = hfpack(tile[o10 + n], tile[o11 + n]);
            }
        }
#pragma unroll
        for (int mt = 0; mt < MT; mt++) {
            int base = ((WOFF + mt * KS + ks) * 32 + lane) * 2;
            uint4 ah = g_wfrag[base];
            uint4 al = g_wfrag[base + 1];
            uint32_t ahi[4] = { ah.x, ah.y, ah.z, ah.w };
            uint32_t alo[4] = { al.x, al.y, al.z, al.w };
#pragma unroll
            for (int r = 0; r < 2; r++)
#pragma unroll
                for (int nt = 0; nt < 4; nt++) {
                    mma_f16(acc[r][mt][nt], ahi, bfr[r][nt]);
                    mma_f16(acc[r][mt][nt], alo, bfr[r][nt]);
                }
        }
    }

#pragma unroll
    for (int r = 0; r < 2; r++) {
        int gy = y0 + r;
#pragma unroll
        for (int mt = 0; mt < MT; mt++) {
            int co0 = mt * 16 + g;
#pragma unroll
            for (int nt = 0; nt < 4; nt++) {
                int px = nbase + nt * 8 + 2 * tig;
                size_t o0 = ((size_t)b * COUT + co0) * SP + (size_t)gy * NYX + px;
                if (PACK_OUT) {
                    uint32_t* op = (uint32_t*)outv;
                    if (co0 < COUT)
                        *reinterpret_cast<uint2*>(op + o0) =
                            make_uint2(hfpack(acc[r][mt][nt][0], acc[r][mt][nt][0]),
                                       hfpack(acc[r][mt][nt][1], acc[r][mt][nt][1]));
                    if (co0 + 8 < COUT)
                        *reinterpret_cast<uint2*>(op + o0 + (size_t)8 * SP) =
                            make_uint2(hfpack(acc[r][mt][nt][2], acc[r][mt][nt][2]),
                                       hfpack(acc[r][mt][nt][3], acc[r][mt][nt][3]));
                } else {
                    float* op = (float*)outv;
                    if (co0 < COUT)
                        *reinterpret_cast<float2*>(op + o0) =
                            make_float2(acc[r][mt][nt][0], acc[r][mt][nt][1]);
                    if (co0 + 8 < COUT)
                        *reinterpret_cast<float2*>(op + o0 + (size_t)8 * SP) =
                            make_float2(acc[r][mt][nt][2], acc[r][mt][nt][3]);
                }
            }
        }
    }
}

// ---------------------------------------------------------------------------
// conv3: fp16 2-pass, input pre-packed duplicated fp16x2. B-build = LDS + PRMT.
// ---------------------------------------------------------------------------
template <int CIN, int MT, int KS, int COUT, int WOFF, int MAXB>
__global__ void __launch_bounds__(256, MAXB)
conv_f16_packed_k(const uint32_t* __restrict__ in, float* __restrict__ out) {
    extern __shared__ float sh[];
    const int ZR = CIN * 3;
    uint32_t* tile = (uint32_t*)sh;
    int* koff = (int*)(sh + (ZR + 1) * TSK);

    const int b  = blockIdx.z;
    const int y0 = blockIdx.y;
    const int tid = threadIdx.y * 32 + threadIdx.x;

    const uint32_t* inb = in + (size_t)b * CIN * SP;
    for (int idx = tid; idx < CIN * 3 * 258; idx += 256) {
        int c  = idx % 258;
        int rr = (idx / 258) % 3;
        int ci = idx / 774;
        int gy = y0 - 1 + rr;
        int gx = c - 1;
        uint32_t v = 0u;
        if (gy >= 0 && gy < NYX && gx >= 0 && gx < NYX)
            v = inb[ci * SP + gy * NYX + gx];
        tile[(ci * 3 + rr) * TSK + 8 * rr + c] = v;
    }
    for (int i = tid; i < TSK; i += 256) tile[ZR * TSK + i] = 0u;
    for (int k = tid; k < KS * 16; k += 256) {
        if (k < CIN * 9) {
            int ci = k / 9, r = k % 9;
            int ky = r / 3;
            koff[k] = (ci * 3 + ky) * TSK + 8 * ky + (r % 3);
        } else {
            koff[k] = ZR * TSK;
        }
    }
    __syncthreads();

    const int warp = threadIdx.y;
    const int lane = threadIdx.x;
    const int g = lane >> 2, tig = lane & 3;
    const int nbase = warp * 32;

    float acc[MT][4][4];
#pragma unroll
    for (int m = 0; m < MT; m++)
#pragma unroll
        for (int n = 0; n < 4; n++)
#pragma unroll
            for (int q = 0; q < 4; q++) acc[m][n][q] = 0.0f;

    for (int ks = 0; ks < KS; ks++) {
        int o00 = koff[ks * 16 + 2 * tig];
        int o01 = koff[ks * 16 + 2 * tig + 1];
        int o10 = koff[ks * 16 + 8 + 2 * tig];
        int o11 = koff[ks * 16 + 8 + 2 * tig + 1];
        uint32_t bfr[4][2];
#pragma unroll
        for (int nt = 0; nt < 4; nt++) {
            int n = nbase + nt * 8 + g;
            // low fp16 of each word -> (lo, hi) pair
            bfr[nt][0] = __byte_perm(tile[o00 + n], tile[o01 + n], 0x5410);
            bfr[nt][1] = __byte_perm(tile[o10 + n], tile[o11 + n], 0x5410);
        }
#pragma unroll
        for (int mt = 0; mt < MT; mt++) {
            int base = ((WOFF + mt * KS + ks) * 32 + lane) * 2;
            uint4 ah = g_wfrag[base];
            uint4 al = g_wfrag[base + 1];
            uint32_t ahi[4] = { ah.x, ah.y, ah.z, ah.w };
            uint32_t alo[4] = { al.x, al.y, al.z, al.w };
#pragma unroll
            for (int nt = 0; nt < 4; nt++) {
                mma_f16(acc[mt][nt], ahi, bfr[nt]);
                mma_f16(acc[mt][nt], alo, bfr[nt]);
            }
        }
    }

#pragma unroll
    for (int mt = 0; mt < MT; mt++) {
        int co0 = mt * 16 + g;
#pragma unroll
        for (int nt = 0; nt < 4; nt++) {
            int px = nbase + nt * 8 + 2 * tig;
            float* op = out + ((size_t)b * COUT + co0) * SP + (size_t)y0 * NYX + px;
            if (co0 < COUT)
                *reinterpret_cast<float2*>(op) = make_float2(acc[mt][nt][0], acc[mt][nt][1]);
            if (co0 + 8 < COUT)
                *reinterpret_cast<float2*>(op + (size_t)8 * SP) = make_float2(acc[mt][nt][2], acc[mt][nt][3]);
        }
    }
}

// ---------------------------------------------------------------------------
__global__ void epiA_scramble_k(float* __restrict__ out) {
    __shared__ float shk[2304], shm1[2304], shm2[2304];
    int b = blockIdx.y;
    int chunk = blockIdx.x;
    int L0 = chunk * 2304;
    int s0 = chunk * 256;
    const float* src = g_p3 + (size_t)b * C3 * SP;
    float* okap = out + OFF_KAP + (size_t)b * 9 * SP;
    float* om   = out + OFF_M   + (size_t)b * 18 * SP;
#pragma unroll
    for (int it = 0; it < 9; ++it) {
        int i = it * 256 + threadIdx.x;
        int L = L0 + i;
        float k  = sp10(src[L]);
        float m1 = src[9 * SP + L];
        float m2 = src[18 * SP + L];
        shk[i] = k; shm1[i] = m1; shm2[i] = m2;
        okap[L] = k;
        om[L] = m1;
        om[9 * SP + L] = m2;
    }
    __syncthreads();
#pragma unroll
    for (int it = 0; it < 9; ++it) {
        int i = it * 256 + threadIdx.x;
        int so = i & 255;
        int t = i >> 8;
        int si = 9 * so + t;
        size_t dst = ((size_t)b * 9 + t) * SP + s0 + so;
        g_kg[dst] = shk[si];
        g_m1[dst] = shm1[si];
        g_m2[dst] = shm2[si];
    }
}

// ---------------------------------------------------------------------------
__global__ void epiH_k(float* __restrict__ out) {
    int gid = blockIdx.x * blockDim.x + threadIdx.x;
    int b = gid >> 16;
    int s = gid & (SP - 1);
    const float* pb = g_p3 + (size_t)b * C3 * SP + s;
    float gm[NT], vx[NT], vy[NT];
#pragma unroll
    for (int t = 0; t < NT; t++) {
        gm[t] = sp10(pb[(size_t)(27 + t) * SP]);
        vx[t] = pb[(size_t)(36 + t) * SP];
        vy[t] = pb[(size_t)(45 + t) * SP];
    }
    const size_t PLANE = (size_t)SP * NT;
    size_t base = OFF_H + (size_t)b * 4 * PLANE + (size_t)s * NT;
#pragma unroll
    for (int t = 0; t < NT; t++) out[base + t] = gm[t] + vx[t] * vx[t];
#pragma unroll
    for (int t = 0; t < NT; t++) {
        float xy = vx[t] * vy[t];
        out[base + PLANE + t]     = xy;
        out[base + 2 * PLANE + t] = xy;
    }
#pragma unroll
    for (int t = 0; t < NT; t++) out[base + 3 * PLANE + t] = gm[t] + vy[t] * vy[t];
}

// ---------------------------------------------------------------------------
__global__ void transpose_k(const float* __restrict__ x) {
    __shared__ float tile[32][33];
    int b = blockIdx.z / NT, t = blockIdx.z % NT;
    const float* xb = x + ((size_t)b * NT + t) * SP;
    float* og = g_xg + ((size_t)b * NT + t) * SP;
    int Y0 = blockIdx.y * 32, X0 = blockIdx.x * 32;
#pragma unroll
    for (int k = 0; k < 4; k++) {
        int row = threadIdx.y + k * 8;
        tile[row][threadIdx.x] = xb[(size_t)(Y0 + row) * NYX + X0 + threadIdx.x];
    }
    __syncthreads();
#pragma unroll
    for (int k = 0; k < 4; k++) {
        int row = threadIdx.y + k * 8;
        og[(size_t)(X0 + row) * NYX + Y0 + threadIdx.x] = tile[threadIdx.x][row];
    }
}

// ---------------------------------------------------------------------------
template <bool QX>
__global__ void applyM_k(const float* __restrict__ u, float* __restrict__ og) {
    __shared__ float tile[10][36];
    __shared__ float red[256];
    int bt = blockIdx.z;
    int b = bt / NT, t = bt % NT;
    int A0 = blockIdx.y * 8, C0 = blockIdx.x * 32;
    const float* ub = u + (size_t)bt * SP;
    int tid = threadIdx.y * 32 + threadIdx.x;
    for (int i = tid; i < 10 * 34; i += 256) {
        int rr = i / 34, cc = i % 34;
        int A = A0 - 1 + rr, C = C0 - 1 + cc;
        tile[rr][cc] = (A >= 0 && A < NYX && C >= 0 && C < NYX)
                       ? ub[(size_t)A * NYX + C] : 0.0f;
    }
    __syncthreads();
    int a = threadIdx.y, c = threadIdx.x;
    float u0 = tile[a + 1][c + 1];
    float xp = tile[a + 2][c + 1], xm = tile[a][c + 1];
    float yp = tile[a + 1][c + 2], ym = tile[a + 1][c];
    float pp = tile[a + 2][c + 2], pm = tile[a + 2][c];
    float mp = tile[a][c + 2],     mm = tile[a][c];
    float dx  = 0.5f * (xp - xm);
    float dy  = 0.5f * (yp - ym);
    float dxx = xp - 2.0f * u0 + xm;
    float dyy = yp - 2.0f * u0 + ym;
    float dxy = 0.25f * (pp - pm - mp + mm);

    int s = (A0 + a) * NYX + (C0 + c);
    size_t pl = (size_t)bt * SP + s;
    const float* pb = g_p3 + (size_t)b * C3 * SP + s;
    float gm = sp10(pb[(size_t)(27 + t) * SP]);
    float vx = pb[(size_t)(36 + t) * SP];
    float vy = pb[(size_t)(45 + t) * SP];
    float kap = g_kg[pl];
    float m1  = g_m1[pl];
    float m2  = g_m2[pl];

    float r = u0 + kap * kap * u0 + m1 * dx + m2 * dy
            - ((gm + vx * vx) * dxx + 2.0f * vx * vy * dxy + (gm + vy * vy) * dyy);

    if (!QX) {
        og[pl] = r;
    } else {
        float xgv = g_xg[pl];
        float q = r;
        if (t >= 1) { q -= u[pl - SP]; }
        if (t <= 7) { q -= u[pl + SP]; }
        if (t >= 1 && t <= 7) q += xgv;
        red[tid] = xgv * q;
        __syncthreads();
        for (int st = 128; st > 0; st >>= 1) {
            if (tid < st) red[tid] += red[tid + st];
            __syncthreads();
        }
        if (tid == 0) {
            int bi = t * 256 + blockIdx.y * 8 + blockIdx.x;
            g_part[b * NPART + bi] = red[0];
        }
    }
}

// ---------------------------------------------------------------------------
__global__ void final_reduce_k(float* __restrict__ out) {
    __shared__ float red[256];
    int b = blockIdx.x;
    float s = 0.0f;
    for (int i = threadIdx.x; i < NPART; i += 256) s += g_part[b * NPART + i];
    red[threadIdx.x] = s;
    __syncthreads();
    for (int st = 128; st > 0; st >>= 1) {
        if (threadIdx.x < st) red[threadIdx.x] += red[threadIdx.x + st];
        __syncthreads();
    }
    if (threadIdx.x == 0) out[OFF_XOUT + b] = red[0];
}

// ---------------------------------------------------------------------------
extern "C" void kernel_launch(void* const* d_in, const int* in_sizes, int n_in,
                              void* d_out, int out_size) {
    const float* x  = (const float*)d_in[0];
    const float* w1 = (const float*)d_in[4];
    const float* w2 = (const float*)d_in[5];
    const float* w3 = (const float*)d_in[6];
    float* out = (float*)d_out;

    float *p1, *p3, *xg, *wg;
    uint32_t* p2;
    cudaGetSymbolAddress((void**)&p1, g_p1);
    cudaGetSymbolAddress((void**)&p2, g_p2);
    cudaGetSymbolAddress((void**)&p3, g_p3);
    cudaGetSymbolAddress((void**)&xg, g_xg);
    cudaGetSymbolAddress((void**)&wg, g_w);

    static cudaStream_t s1 = nullptr;
    static cudaEvent_t ev0 = nullptr, evT = nullptr, evC = nullptr, ev1 = nullptr;
    if (!s1) {
        cudaStreamCreateWithFlags(&s1, cudaStreamNonBlocking);
        cudaEventCreateWithFlags(&ev0, cudaEventDisableTiming);
        cudaEventCreateWithFlags(&evT, cudaEventDisableTiming);
        cudaEventCreateWithFlags(&evC, cudaEventDisableTiming);
        cudaEventCreateWithFlags(&ev1, cudaEventDisableTiming);
    }

    const int smem1 = (9  * 4 + 1) * TSK * 4 + 2 * 6 * 16 * 4;   // 43,392
    const int smem2 = (10 * 4 + 1) * TSK * 4 + 2 * 6 * 16 * 4;   // 48,000
    const int smem3 = (20 * 3 + 1) * TSK * 4 + 12 * 16 * 4;      // 71,040
    cudaFuncSetAttribute((const void*)conv_f16_2r_k<9,  true, 1, 6, C1, 0, 3, false>, cudaFuncAttributeMaxDynamicSharedMemorySize, smem1);
    cudaFuncSetAttribute((const void*)conv_f16_2r_k<10, true, 2, 6, C2, 6, 2, true >, cudaFuncAttributeMaxDynamicSharedMemorySize, smem2);
    cudaFuncSetAttribute((const void*)conv_f16_packed_k<20, 4, 12, C3, 18, 2>, cudaFuncAttributeMaxDynamicSharedMemorySize, smem3);

    // fork: transpose on side stream
    cudaEventRecord(ev0, 0);
    cudaStreamWaitEvent(s1, ev0, 0);
    transpose_k<<<dim3(8, 8, NB * NT), dim3(32, 8), 0, s1>>>(x);
    cudaEventRecord(evT, s1);

    // main: conv chain
    prep_w_k<<<9, 256>>>(w1, w2, w3);
    conv_f16_2r_k<9,  true, 1, 6, C1, 0, 3, false><<<dim3(1, 128, NB), dim3(32, 8), smem1>>>(x,  p1);
    conv_f16_2r_k<10, true, 2, 6, C2, 6, 2, true ><<<dim3(1, 128, NB), dim3(32, 8), smem2>>>(p1, p2);
    conv_f16_packed_k<20, 4, 12, C3, 18, 2><<<dim3(1, 256, NB), dim3(32, 8), smem3>>>(p2, p3);
    cudaEventRecord(evC, 0);

    // side: epiH
    cudaStreamWaitEvent(s1, evC, 0);
    epiH_k<<<(NB * SP) / 256, 256, 0, s1>>>(out);
    cudaEventRecord(ev1, s1);

    // main: epiA -> PDE pipeline (v-pass fused with qx)
    epiA_scramble_k<<<dim3(256, NB), 256>>>(out);
    cudaStreamWaitEvent(0, evT, 0);
    applyM_k<false><<<dim3(8, 32, NB * NT), dim3(32, 8)>>>(xg, wg);
    applyM_k<true ><<<dim3(8, 32, NB * NT), dim3(32, 8)>>>(wg, nullptr);
    cudaStreamWaitEvent(0, ev1, 0);
    final_reduce_k<<<NB, 256>>>(out);
}

// round 17
// speedup vs baseline: 1.2046x; 1.0658x over previous
#include <cuda_runtime.h>
#include <cuda_bf16.h>
#include <cstdint>

#define NB 16
#define NT 9
#define NYX 256
#define SP 65536
#define C1 10
#define C2 20
#define C3 54

#define OFF_XOUT 0
#define OFF_KAP  16
#define OFF_M    9437200
#define OFF_H    28311568

#define TSK 288
#define NPART 2304

__device__ uint32_t g_p1[NB * C1 * SP];   // relu'd, duplicated fp16x2
__device__ uint32_t g_p2[NB * C2 * SP];   // duplicated fp16x2
__device__ float    g_p3[NB * C3 * SP];
__device__ float g_xg[NB * NT * SP];
__device__ float g_w [NB * NT * SP];
__device__ float g_kg [NB * NT * SP];
__device__ float g_m1 [NB * NT * SP];
__device__ float g_m2 [NB * NT * SP];
__device__ float g_part[NB * NPART];
// fp16 A-fragments (hi,lo): conv1 slots 0..5 (MT1,KS6); conv2 6..17 (MT2,KS6);
// conv3 18..65 (MT4,KS12).
__device__ uint4 g_wfrag[66 * 32 * 2];

__device__ __forceinline__ float sp10(float x) {
    float z = 10.0f * x;
    return (fmaxf(z, 0.0f) + log1pf(expf(-fabsf(z)))) * 0.1f;
}
__device__ __forceinline__ uint32_t hfpack(float lo, float hi) {
    uint32_t r; asm("cvt.rn.f16x2.f32 %0, %1, %2;" : "=r"(r) : "f"(hi), "f"(lo));
    return r;
}
__device__ __forceinline__ void mma_f16(float* d, const uint32_t* a, const uint32_t* b) {
    asm("mma.sync.aligned.m16n8k16.row.col.f32.f16.f16.f32 "
        "{%0,%1,%2,%3}, {%4,%5,%6,%7}, {%8,%9}, {%0,%1,%2,%3};"
        : "+f"(d[0]), "+f"(d[1]), "+f"(d[2]), "+f"(d[3])
        : "r"(a[0]), "r"(a[1]), "r"(a[2]), "r"(a[3]), "r"(b[0]), "r"(b[1]));
}

// ---------------------------------------------------------------------------
__global__ void prep_w_k(const float* __restrict__ w1,
                         const float* __restrict__ w2,
                         const float* __restrict__ w3) {
    int idx = blockIdx.x * blockDim.x + threadIdx.x;
    if (idx >= 66 * 32) return;
    int lane = idx & 31;
    int slot = idx >> 5;
    const float* w; int K, COUT, mt, ks;
    if (slot < 6)       { w = w1; K = 81;  COUT = C1; mt = 0;               ks = slot; }
    else if (slot < 18) { w = w2; K = 90;  COUT = C2; int s = slot - 6;  mt = s / 6;  ks = s % 6; }
    else                { w = w3; K = 180; COUT = C3; int s = slot - 18; mt = s / 12; ks = s % 12; }
    int g = lane >> 2, tig = lane & 3;
    uint32_t hi[4], lo[4];
#pragma unroll
    for (int i = 0; i < 4; i++) {
        int row = mt * 16 + g + (i & 1) * 8;
        int k   = ks * 16 + (i >> 1) * 8 + 2 * tig;
        float w0 = (row < COUT && k     < K) ? w[row * K + k]     : 0.0f;
        float w1v = (row < COUT && k + 1 < K) ? w[row * K + k + 1] : 0.0f;
        float h0 = __half2float(__float2half_rn(w0));
        float h1 = __half2float(__float2half_rn(w1v));
        hi[i] = hfpack(h0, h1);
        lo[i] = hfpack(w0 - h0, w1v - h1);
    }
    int base = (slot * 32 + lane) * 2;
    g_wfrag[base]     = make_uint4(hi[0], hi[1], hi[2], hi[3]);
    g_wfrag[base + 1] = make_uint4(lo[0], lo[1], lo[2], lo[3]);
}

// ---------------------------------------------------------------------------
// conv1: fp16 2-pass, two output rows per block (f32 input, relu-in).
// Writes relu'd duplicated fp16x2.
// ---------------------------------------------------------------------------
template <int CIN, int MT, int KS, int COUT, int WOFF, int MAXB>
__global__ void __launch_bounds__(256, MAXB)
conv_f16_2r_k(const float* __restrict__ in, uint32_t* __restrict__ out) {
    extern __shared__ float sh[];
    const int ZR = CIN * 4;
    float* tile = sh;
    int* koff = (int*)(sh + (ZR + 1) * TSK);

    const int b  = blockIdx.z;
    const int y0 = blockIdx.y * 2;
    const int tid = threadIdx.y * 32 + threadIdx.x;

    const float* inb = in + (size_t)b * CIN * SP;
    for (int idx = tid; idx < CIN * 4 * 258; idx += 256) {
        int c  = idx % 258;
        int rr = (idx / 258) & 3;
        int ci = idx / (258 * 4);
        int gy = y0 - 1 + rr;
        int gx = c - 1;
        float v = 0.0f;
        if (gy >= 0 && gy < NYX && gx >= 0 && gx < NYX)
            v = fmaxf(inb[ci * SP + gy * NYX + gx], 0.0f);
        tile[(ci * 4 + rr) * TSK + 8 * (rr % 3) + c] = v;
    }
    for (int i = tid; i < TSK; i += 256) tile[ZR * TSK + i] = 0.0f;
    for (int k = tid; k < 2 * KS * 16; k += 256) {
        int r  = k / (KS * 16);
        int kk = k % (KS * 16);
        int off;
        if (kk < CIN * 9) {
            int ci = kk / 9, tap = kk % 9;
            int ky = tap / 3;
            int rr = ky + r;
            off = (ci * 4 + rr) * TSK + 8 * (rr % 3) + tap % 3;
        } else off = ZR * TSK;
        koff[k] = off;
    }
    __syncthreads();

    const int warp = threadIdx.y;
    const int lane = threadIdx.x;
    const int g = lane >> 2, tig = lane & 3;
    const int nbase = warp * 32;

    float acc[2][MT][4][4];
#pragma unroll
    for (int r = 0; r < 2; r++)
#pragma unroll
        for (int m = 0; m < MT; m++)
#pragma unroll
            for (int n = 0; n < 4; n++)
#pragma unroll
                for (int q = 0; q < 4; q++) acc[r][m][n][q] = 0.0f;

    for (int ks = 0; ks < KS; ks++) {
        uint32_t bfr[2][4][2];
#pragma unroll
        for (int r = 0; r < 2; r++) {
            const int* kf = koff + r * KS * 16 + ks * 16;
            int o00 = kf[2 * tig], o01 = kf[2 * tig + 1];
            int o10 = kf[8 + 2 * tig], o11 = kf[8 + 2 * tig + 1];
#pragma unroll
            for (int nt = 0; nt < 4; nt++) {
                int n = nbase + nt * 8 + g;
                bfr[r][nt][0] = hfpack(tile[o00 + n], tile[o01 + n]);
                bfr[r][nt][1] = hfpack(tile[o10 + n], tile[o11 + n]);
            }
        }
#pragma unroll
        for (int mt = 0; mt < MT; mt++) {
            int base = ((WOFF + mt * KS + ks) * 32 + lane) * 2;
            uint4 ah = g_wfrag[base];
            uint4 al = g_wfrag[base + 1];
            uint32_t ahi[4] = { ah.x, ah.y, ah.z, ah.w };
            uint32_t alo[4] = { al.x, al.y, al.z, al.w };
#pragma unroll
            for (int r = 0; r < 2; r++)
#pragma unroll
                for (int nt = 0; nt < 4; nt++) {
                    mma_f16(acc[r][mt][nt], ahi, bfr[r][nt]);
                    mma_f16(acc[r][mt][nt], alo, bfr[r][nt]);
                }
        }
    }

#pragma unroll
    for (int r = 0; r < 2; r++) {
        int gy = y0 + r;
#pragma unroll
        for (int mt = 0; mt < MT; mt++) {
            int co0 = mt * 16 + g;
#pragma unroll
            for (int nt = 0; nt < 4; nt++) {
                int px = nbase + nt * 8 + 2 * tig;
                size_t o0 = ((size_t)b * COUT + co0) * SP + (size_t)gy * NYX + px;
                float v0 = fmaxf(acc[r][mt][nt][0], 0.0f), v1 = fmaxf(acc[r][mt][nt][1], 0.0f);
                float v2 = fmaxf(acc[r][mt][nt][2], 0.0f), v3 = fmaxf(acc[r][mt][nt][3], 0.0f);
                if (co0 < COUT)
                    *reinterpret_cast<uint2*>(out + o0) =
                        make_uint2(hfpack(v0, v0), hfpack(v1, v1));
                if (co0 + 8 < COUT)
                    *reinterpret_cast<uint2*>(out + o0 + (size_t)8 * SP) =
                        make_uint2(hfpack(v2, v2), hfpack(v3, v3));
            }
        }
    }
}

// ---------------------------------------------------------------------------
// Ring conv: strip of R rows per block, 4-slice ring, cp.async prefetch.
// Input: duplicated fp16x2 u32. PACK_OUT: pack output (conv2) else f32 (conv3).
// Slice addr: (ci*4+p)*TSK + 8*p + c, p = src_row & 3.
// ---------------------------------------------------------------------------
template <int CIN, int MT, int KS, int COUT, int WOFF, int R, bool PACK_OUT>
__global__ void __launch_bounds__(256, 2)
conv_ring_k(const uint32_t* __restrict__ in, void* __restrict__ outv) {
    extern __shared__ float shf[];
    uint32_t* tile = (uint32_t*)shf;                 // CIN*4*TSK
    int* enc = (int*)(tile + CIN * 4 * TSK);         // KS*16

    const int b   = blockIdx.z;
    const int gy0 = blockIdx.y * R;
    const int tid = threadIdx.y * 32 + threadIdx.x;
    const uint32_t* inb = in + (size_t)b * CIN * SP;
    const uint32_t smem_base = (uint32_t)__cvta_generic_to_shared(tile);

    for (int k = tid; k < KS * 16; k += 256) {
        int e = 0;
        if (k < CIN * 9) {
            int ci = k / 9, tap = k % 9;
            e = (ci * 4 * TSK + tap % 3) | ((tap / 3) << 26);
        }
        enc[k] = e;
    }

    auto fill_slice = [&](int gsrc) {
        int p = gsrc & 3;
        bool rowok = (gsrc >= 0 && gsrc < NYX);
        const uint32_t* src = inb + (size_t)gsrc * NYX;
        for (int idx = tid; idx < CIN * 258; idx += 256) {
            int ci = idx / 258, c = idx % 258;
            uint32_t soff = (uint32_t)((ci * 4 + p) * TSK + 8 * p + c);
            if (rowok && c >= 1 && c <= 256) {
                uint32_t sa = smem_base + soff * 4;
                asm volatile("cp.async.ca.shared.global [%0], [%1], 4;"
                             :: "r"(sa), "l"(src + (size_t)ci * SP + (c - 1)) : "memory");
            } else {
                tile[soff] = 0u;
            }
        }
    };

    fill_slice(gy0 - 1);
    fill_slice(gy0);
    fill_slice(gy0 + 1);
    asm volatile("cp.async.commit_group;" ::: "memory");
    asm volatile("cp.async.wait_group 0;" ::: "memory");
    __syncthreads();

    const int warp = threadIdx.y;
    const int lane = threadIdx.x;
    const int g = lane >> 2, tig = lane & 3;
    const int nbase = warp * 32;

    for (int y = 0; y < R; ++y) {
        const int gy = gy0 + y;
        // prefetch slice gy+2 (targets phase (gy+2)&3 — not read this row)
        fill_slice(gy + 2);
        asm volatile("cp.async.commit_group;" ::: "memory");

        float acc[MT][4][4];
#pragma unroll
        for (int m = 0; m < MT; m++)
#pragma unroll
            for (int n = 0; n < 4; n++)
#pragma unroll
                for (int q = 0; q < 4; q++) acc[m][n][q] = 0.0f;

        for (int ks = 0; ks < KS; ks++) {
            int e00 = enc[ks * 16 + 2 * tig];
            int e01 = enc[ks * 16 + 2 * tig + 1];
            int e10 = enc[ks * 16 + 8 + 2 * tig];
            int e11 = enc[ks * 16 + 8 + 2 * tig + 1];
            int o00 = (e00 & 0x03FFFFFF) + (((gy + 3 + (e00 >> 26)) & 3) * (TSK + 8));
            int o01 = (e01 & 0x03FFFFFF) + (((gy + 3 + (e01 >> 26)) & 3) * (TSK + 8));
            int o10 = (e10 & 0x03FFFFFF) + (((gy + 3 + (e10 >> 26)) & 3) * (TSK + 8));
            int o11 = (e11 & 0x03FFFFFF) + (((gy + 3 + (e11 >> 26)) & 3) * (TSK + 8));
            uint32_t bfr[4][2];
#pragma unroll
            for (int nt = 0; nt < 4; nt++) {
                int n = nbase + nt * 8 + g;
                bfr[nt][0] = __byte_perm(tile[o00 + n], tile[o01 + n], 0x5410);
                bfr[nt][1] = __byte_perm(tile[o10 + n], tile[o11 + n], 0x5410);
            }
#pragma unroll
            for (int mt = 0; mt < MT; mt++) {
                int base = ((WOFF + mt * KS + ks) * 32 + lane) * 2;
                uint4 ah = g_wfrag[base];
                uint4 al = g_wfrag[base + 1];
                uint32_t ahi[4] = { ah.x, ah.y, ah.z, ah.w };
                uint32_t alo[4] = { al.x, al.y, al.z, al.w };
#pragma unroll
                for (int nt = 0; nt < 4; nt++) {
                    mma_f16(acc[mt][nt], ahi, bfr[nt]);
                    mma_f16(acc[mt][nt], alo, bfr[nt]);
                }
            }
        }

#pragma unroll
        for (int mt = 0; mt < MT; mt++) {
            int co0 = mt * 16 + g;
#pragma unroll
            for (int nt = 0; nt < 4; nt++) {
                int px = nbase + nt * 8 + 2 * tig;
                size_t o0 = ((size_t)b * COUT + co0) * SP + (size_t)gy * NYX + px;
                if (PACK_OUT) {
                    uint32_t* op = (uint32_t*)outv;
                    if (co0 < COUT)
                        *reinterpret_cast<uint2*>(op + o0) =
                            make_uint2(hfpack(acc[mt][nt][0], acc[mt][nt][0]),
                                       hfpack(acc[mt][nt][1], acc[mt][nt][1]));
                    if (co0 + 8 < COUT)
                        *reinterpret_cast<uint2*>(op + o0 + (size_t)8 * SP) =
                            make_uint2(hfpack(acc[mt][nt][2], acc[mt][nt][2]),
                                       hfpack(acc[mt][nt][3], acc[mt][nt][3]));
                } else {
                    float* op = (float*)outv;
                    if (co0 < COUT)
                        *reinterpret_cast<float2*>(op + o0) =
                            make_float2(acc[mt][nt][0], acc[mt][nt][1]);
                    if (co0 + 8 < COUT)
                        *reinterpret_cast<float2*>(op + o0 + (size_t)8 * SP) =
                            make_float2(acc[mt][nt][2], acc[mt][nt][3]);
                }
            }
        }

        asm volatile("cp.async.wait_group 0;" ::: "memory");
        __syncthreads();
    }
}

// ---------------------------------------------------------------------------
__global__ void epiA_scramble_k(float* __restrict__ out) {
    __shared__ float shk[2304], shm1[2304], shm2[2304];
    int b = blockIdx.y;
    int chunk = blockIdx.x;
    int L0 = chunk * 2304;
    int s0 = chunk * 256;
    const float* src = g_p3 + (size_t)b * C3 * SP;
    float* okap = out + OFF_KAP + (size_t)b * 9 * SP;
    float* om   = out + OFF_M   + (size_t)b * 18 * SP;
#pragma unroll
    for (int it = 0; it < 9; ++it) {
        int i = it * 256 + threadIdx.x;
        int L = L0 + i;
        float k  = sp10(src[L]);
        float m1 = src[9 * SP + L];
        float m2 = src[18 * SP + L];
        shk[i] = k; shm1[i] = m1; shm2[i] = m2;
        okap[L] = k;
        om[L] = m1;
        om[9 * SP + L] = m2;
    }
    __syncthreads();
#pragma unroll
    for (int it = 0; it < 9; ++it) {
        int i = it * 256 + threadIdx.x;
        int so = i & 255;
        int t = i >> 8;
        int si = 9 * so + t;
        size_t dst = ((size_t)b * 9 + t) * SP + s0 + so;
        g_kg[dst] = shk[si];
        g_m1[dst] = shm1[si];
        g_m2[dst] = shm2[si];
    }
}

// ---------------------------------------------------------------------------
__global__ void epiH_k(float* __restrict__ out) {
    int gid = blockIdx.x * blockDim.x + threadIdx.x;
    int b = gid >> 16;
    int s = gid & (SP - 1);
    const float* pb = g_p3 + (size_t)b * C3 * SP + s;
    float gm[NT], vx[NT], vy[NT];
#pragma unroll
    for (int t = 0; t < NT; t++) {
        gm[t] = sp10(pb[(size_t)(27 + t) * SP]);
        vx[t] = pb[(size_t)(36 + t) * SP];
        vy[t] = pb[(size_t)(45 + t) * SP];
    }
    const size_t PLANE = (size_t)SP * NT;
    size_t base = OFF_H + (size_t)b * 4 * PLANE + (size_t)s * NT;
#pragma unroll
    for (int t = 0; t < NT; t++) out[base + t] = gm[t] + vx[t] * vx[t];
#pragma unroll
    for (int t = 0; t < NT; t++) {
        float xy = vx[t] * vy[t];
        out[base + PLANE + t]     = xy;
        out[base + 2 * PLANE + t] = xy;
    }
#pragma unroll
    for (int t = 0; t < NT; t++) out[base + 3 * PLANE + t] = gm[t] + vy[t] * vy[t];
}

// ---------------------------------------------------------------------------
__global__ void transpose_k(const float* __restrict__ x) {
    __shared__ float tile[32][33];
    int b = blockIdx.z / NT, t = blockIdx.z % NT;
    const float* xb = x + ((size_t)b * NT + t) * SP;
    float* og = g_xg + ((size_t)b * NT + t) * SP;
    int Y0 = blockIdx.y * 32, X0 = blockIdx.x * 32;
#pragma unroll
    for (int k = 0; k < 4; k++) {
        int row = threadIdx.y + k * 8;
        tile[row][threadIdx.x] = xb[(size_t)(Y0 + row) * NYX + X0 + threadIdx.x];
    }
    __syncthreads();
#pragma unroll
    for (int k = 0; k < 4; k++) {
        int row = threadIdx.y + k * 8;
        og[(size_t)(X0 + row) * NYX + Y0 + threadIdx.x] = tile[threadIdx.x][row];
    }
}

// ---------------------------------------------------------------------------
template <bool QX>
__global__ void applyM_k(const float* __restrict__ u, float* __restrict__ og) {
    __shared__ float tile[10][36];
    __shared__ float red[256];
    int bt = blockIdx.z;
    int b = bt / NT, t = bt % NT;
    int A0 = blockIdx.y * 8, C0 = blockIdx.x * 32;
    const float* ub = u + (size_t)bt * SP;
    int tid = threadIdx.y * 32 + threadIdx.x;
    for (int i = tid; i < 10 * 34; i += 256) {
        int rr = i / 34, cc = i % 34;
        int A = A0 - 1 + rr, C = C0 - 1 + cc;
        tile[rr][cc] = (A >= 0 && A < NYX && C >= 0 && C < NYX)
                       ? ub[(size_t)A * NYX + C] : 0.0f;
    }
    __syncthreads();
    int a = threadIdx.y, c = threadIdx.x;
    float u0 = tile[a + 1][c + 1];
    float xp = tile[a + 2][c + 1], xm = tile[a][c + 1];
    float yp = tile[a + 1][c + 2], ym = tile[a + 1][c];
    float pp = tile[a + 2][c + 2], pm = tile[a + 2][c];
    float mp = tile[a][c + 2],     mm = tile[a][c];
    float dx  = 0.5f * (xp - xm);
    float dy  = 0.5f * (yp - ym);
    float dxx = xp - 2.0f * u0 + xm;
    float dyy = yp - 2.0f * u0 + ym;
    float dxy = 0.25f * (pp - pm - mp + mm);

    int s = (A0 + a) * NYX + (C0 + c);
    size_t pl = (size_t)bt * SP + s;
    const float* pb = g_p3 + (size_t)b * C3 * SP + s;
    float gm = sp10(pb[(size_t)(27 + t) * SP]);
    float vx = pb[(size_t)(36 + t) * SP];
    float vy = pb[(size_t)(45 + t) * SP];
    float kap = g_kg[pl];
    float m1  = g_m1[pl];
    float m2  = g_m2[pl];

    float r = u0 + kap * kap * u0 + m1 * dx + m2 * dy
            - ((gm + vx * vx) * dxx + 2.0f * vx * vy * dxy + (gm + vy * vy) * dyy);

    if (!QX) {
        og[pl] = r;
    } else {
        float xgv = g_xg[pl];
        float q = r;
        if (t >= 1) { q -= u[pl - SP]; }
        if (t <= 7) { q -= u[pl + SP]; }
        if (t >= 1 && t <= 7) q += xgv;
        red[tid] = xgv * q;
        __syncthreads();
        for (int st = 128; st > 0; st >>= 1) {
            if (tid < st) red[tid] += red[tid + st];
            __syncthreads();
        }
        if (tid == 0) {
            int bi = t * 256 + blockIdx.y * 8 + blockIdx.x;
            g_part[b * NPART + bi] = red[0];
        }
    }
}

// ---------------------------------------------------------------------------
__global__ void final_reduce_k(float* __restrict__ out) {
    __shared__ float red[256];
    int b = blockIdx.x;
    float s = 0.0f;
    for (int i = threadIdx.x; i < NPART; i += 256) s += g_part[b * NPART + i];
    red[threadIdx.x] = s;
    __syncthreads();
    for (int st = 128; st > 0; st >>= 1) {
        if (threadIdx.x < st) red[threadIdx.x] += red[threadIdx.x + st];
        __syncthreads();
    }
    if (threadIdx.x == 0) out[OFF_XOUT + b] = red[0];
}

// ---------------------------------------------------------------------------
extern "C" void kernel_launch(void* const* d_in, const int* in_sizes, int n_in,
                              void* d_out, int out_size) {
    const float* x  = (const float*)d_in[0];
    const float* w1 = (const float*)d_in[4];
    const float* w2 = (const float*)d_in[5];
    const float* w3 = (const float*)d_in[6];
    float* out = (float*)d_out;

    float *p3, *xg, *wg;
    uint32_t *p1, *p2;
    cudaGetSymbolAddress((void**)&p1, g_p1);
    cudaGetSymbolAddress((void**)&p2, g_p2);
    cudaGetSymbolAddress((void**)&p3, g_p3);
    cudaGetSymbolAddress((void**)&xg, g_xg);
    cudaGetSymbolAddress((void**)&wg, g_w);

    static cudaStream_t s1 = nullptr;
    static cudaEvent_t ev0 = nullptr, evT = nullptr, evC = nullptr, ev1 = nullptr;
    if (!s1) {
        cudaStreamCreateWithFlags(&s1, cudaStreamNonBlocking);
        cudaEventCreateWithFlags(&ev0, cudaEventDisableTiming);
        cudaEventCreateWithFlags(&evT, cudaEventDisableTiming);
        cudaEventCreateWithFlags(&evC, cudaEventDisableTiming);
        cudaEventCreateWithFlags(&ev1, cudaEventDisableTiming);
    }

    const int smem1 = (9 * 4 + 1) * TSK * 4 + 2 * 6 * 16 * 4;      // 43,392
    const int smem2 = 10 * 4 * TSK * 4 + 6 * 16 * 4;               // 46,464
    const int smem3 = 20 * 4 * TSK * 4 + 12 * 16 * 4;              // 92,928
    cudaFuncSetAttribute((const void*)conv_f16_2r_k<9, 1, 6, C1, 0, 3>, cudaFuncAttributeMaxDynamicSharedMemorySize, smem1);
    cudaFuncSetAttribute((const void*)conv_ring_k<10, 2, 6,  C2, 6,  16, true >, cudaFuncAttributeMaxDynamicSharedMemorySize, smem2);
    cudaFuncSetAttribute((const void*)conv_ring_k<20, 4, 12, C3, 18, 16, false>, cudaFuncAttributeMaxDynamicSharedMemorySize, smem3);

    // fork: transpose on side stream
    cudaEventRecord(ev0, 0);
    cudaStreamWaitEvent(s1, ev0, 0);
    transpose_k<<<dim3(8, 8, NB * NT), dim3(32, 8), 0, s1>>>(x);
    cudaEventRecord(evT, s1);

    // main: conv chain
    prep_w_k<<<9, 256>>>(w1, w2, w3);
    conv_f16_2r_k<9, 1, 6, C1, 0, 3><<<dim3(1, 128, NB), dim3(32, 8), smem1>>>(x, p1);
    conv_ring_k<10, 2, 6,  C2, 6,  16, true ><<<dim3(1, 16, NB), dim3(32, 8), smem2>>>(p1, p2);
    conv_ring_k<20, 4, 12, C3, 18, 16, false><<<dim3(1, 16, NB), dim3(32, 8), smem3>>>(p2, p3);
    cudaEventRecord(evC, 0);

    // side: epiH
    cudaStreamWaitEvent(s1, evC, 0);
    epiH_k<<<(NB * SP) / 256, 256, 0, s1>>>(out);
    cudaEventRecord(ev1, s1);

    // main: epiA -> PDE pipeline (v-pass fused with qx)
    epiA_scramble_k<<<dim3(256, NB), 256>>>(out);
    cudaStreamWaitEvent(0, evT, 0);
    applyM_k<false><<<dim3(8, 32, NB * NT), dim3(32, 8)>>>(xg, wg);
    applyM_k<true ><<<dim3(8, 32, NB * NT), dim3(32, 8)>>>(wg, nullptr);
    cudaStreamWaitEvent(0, ev1, 0);
    final_reduce_k<<<NB, 256>>>(out);
}